// round 5
// baseline (speedup 1.0000x reference)
#include <cuda_runtime.h>
#include <cuda_bf16.h>
#include <mma.h>

using namespace nvcuda;

#define DIMC    1024
#define NHEADS  16
#define HDIM    64
#define BATCH   4
#define SEQ     2048
#define MTOT    (BATCH*SEQ)      // 8192
#define ATT_SCALE 0.125f         // 64^-0.5

// ---------------- scratch (static device globals; no allocation) ----------------
__device__ float g_Q[(size_t)BATCH*NHEADS*SEQ*HDIM];   // [B,H,N,Dh]
__device__ float g_K[(size_t)BATCH*NHEADS*SEQ*HDIM];
__device__ float g_V[(size_t)BATCH*NHEADS*SEQ*HDIM];
__device__ float g_AO[(size_t)MTOT*DIMC];              // [B,N,H,Dh] == [M, C]

// round-to-nearest fp32 -> tf32 (bit pattern in a b32 reg). RNA is load-bearing:
// truncation would bias dot products by ~1e-3 relative.
__device__ __forceinline__ unsigned f2tf(float f) {
    unsigned u;
    asm("cvt.rna.tf32.f32 %0, %1;" : "=r"(u) : "f"(f));
    return u;
}

__device__ __forceinline__ void mma_tf32(float c[4], const unsigned a[4],
                                         unsigned b0, unsigned b1) {
    asm volatile(
        "mma.sync.aligned.m16n8k8.row.col.f32.tf32.tf32.f32 "
        "{%0,%1,%2,%3},{%4,%5,%6,%7},{%8,%9},{%0,%1,%2,%3};"
        : "+f"(c[0]), "+f"(c[1]), "+f"(c[2]), "+f"(c[3])
        : "r"(a[0]), "r"(a[1]), "r"(a[2]), "r"(a[3]), "r"(b0), "r"(b1));
}

// ================================================================================
// TF32 GEMM: C[M,N] = A[M,K] @ W[N,K]^T   (both row-major, torch Linear weight)
// Block tile 128x128, BK=16, 8 warps (2 m x 4 n), warp tile 64x32.
// EPI==0: scatter into g_Q/g_K/g_V per qkv column semantics (col j = t*1024+h*64+d)
// EPI==1: A is g_AO, store into Out (row-major, ld=N); bias added by a later kernel.
// ================================================================================
template<int EPI>
__global__ __launch_bounds__(256)
void gemm_tf32_kernel(const float* __restrict__ A_in,
                      const float* __restrict__ W,
                      float* __restrict__ Out,
                      int M, int N, int K)
{
    constexpr int BM = 128, BN = 128, BK = 16, BKP = 20;
    __shared__ float As[BM][BKP];
    __shared__ float Bs[BN][BKP];

    const float* A = (EPI == 1) ? (const float*)g_AO : A_in;

    const int tid = threadIdx.x;
    const int wid = tid >> 5;
    const int wm  = wid & 1;        // 0..1
    const int wn  = wid >> 1;       // 0..3
    const int m0  = blockIdx.y * BM;
    const int cn  = blockIdx.x * BN;

    wmma::fragment<wmma::accumulator, 16, 16, 8, float> acc[4][2];
#pragma unroll
    for (int mt = 0; mt < 4; mt++)
#pragma unroll
        for (int nt = 0; nt < 2; nt++)
            wmma::fill_fragment(acc[mt][nt], 0.0f);

    for (int k0 = 0; k0 < K; k0 += BK) {
        // stage A tile: 128x16 = 512 float4
#pragma unroll
        for (int it = 0; it < 2; it++) {
            int lin = tid + it * 256;       // 0..511
            int row = lin >> 2, q = lin & 3;
            float4 v = *(const float4*)(A + (size_t)(m0 + row) * K + k0 + q * 4);
            As[row][q * 4 + 0] = v.x;
            As[row][q * 4 + 1] = v.y;
            As[row][q * 4 + 2] = v.z;
            As[row][q * 4 + 3] = v.w;
        }
        // stage B tile (W rows cn..cn+127)
#pragma unroll
        for (int it = 0; it < 2; it++) {
            int lin = tid + it * 256;
            int row = lin >> 2, q = lin & 3;
            float4 v = *(const float4*)(W + (size_t)(cn + row) * K + k0 + q * 4);
            Bs[row][q * 4 + 0] = v.x;
            Bs[row][q * 4 + 1] = v.y;
            Bs[row][q * 4 + 2] = v.z;
            Bs[row][q * 4 + 3] = v.w;
        }
        __syncthreads();

#pragma unroll
        for (int ks = 0; ks < BK; ks += 8) {
            wmma::fragment<wmma::matrix_a, 16, 16, 8, wmma::precision::tf32,
                           wmma::row_major> af[4];
            wmma::fragment<wmma::matrix_b, 16, 16, 8, wmma::precision::tf32,
                           wmma::col_major> bf[2];
#pragma unroll
            for (int mt = 0; mt < 4; mt++) {
                wmma::load_matrix_sync(af[mt], &As[wm * 64 + mt * 16][ks], BKP);
#pragma unroll
                for (int i = 0; i < af[mt].num_elements; i++)
                    af[mt].x[i] = wmma::__float_to_tf32(af[mt].x[i]);
            }
#pragma unroll
            for (int nt = 0; nt < 2; nt++) {
                wmma::load_matrix_sync(bf[nt], &Bs[wn * 32 + nt * 16][ks], BKP);
#pragma unroll
                for (int i = 0; i < bf[nt].num_elements; i++)
                    bf[nt].x[i] = wmma::__float_to_tf32(bf[nt].x[i]);
            }
#pragma unroll
            for (int mt = 0; mt < 4; mt++)
#pragma unroll
                for (int nt = 0; nt < 2; nt++)
                    wmma::mma_sync(acc[mt][nt], af[mt], bf[nt], acc[mt][nt]);
        }
        __syncthreads();
    }

    // epilogue
#pragma unroll
    for (int mt = 0; mt < 4; mt++) {
#pragma unroll
        for (int nt = 0; nt < 2; nt++) {
            int j0 = cn + wn * 32 + nt * 16;
            int mg = m0 + wm * 64 + mt * 16;
            if (EPI == 0) {
                // column j = t*1024 + h*64 + d ; row m = b*2048 + n
                int t = j0 >> 10, r = j0 & 1023, h = r >> 6, d0 = r & 63;
                int b = mg >> 11, n0 = mg & 2047;
                float* base = (t == 0) ? g_Q : ((t == 1) ? g_K : g_V);
                wmma::store_matrix_sync(
                    base + (((size_t)(b * NHEADS + h) * SEQ + n0) * HDIM + d0),
                    acc[mt][nt], HDIM, wmma::mem_row_major);
            } else {
                wmma::store_matrix_sync(Out + (size_t)mg * N + j0,
                                        acc[mt][nt], N, wmma::mem_row_major);
            }
        }
    }
}

// ================================================================================
// Flash attention: grid (N/64, B*H), 128 threads (4 warps), each warp owns 16 q rows
// (rows lane/4 and lane/4+8 per mma group) -> softmax fully warp-local.
// S = (Q*scale) K^T via mma.m16n8k8.tf32 ; P repacked via smem (Ks reused as Ps).
// ================================================================================
__global__ __launch_bounds__(128)
void attn_kernel()
{
    __shared__ float Ks[64][68];   // keys x d ; reused as P (64 q-rows x 64 keys)
    __shared__ float Vs[64][72];   // keys x d

    const int tid = threadIdx.x;
    const int w   = tid >> 5;
    const int lane = tid & 31;
    const int g   = lane >> 2;     // groupID
    const int t4  = lane & 3;      // threadID_in_group

    const int bh = blockIdx.y;
    const float* Qg = g_Q + (size_t)bh * SEQ * HDIM;
    const float* Kg = g_K + (size_t)bh * SEQ * HDIM;
    const float* Vg = g_V + (size_t)bh * SEQ * HDIM;

    const int q0 = blockIdx.x * 64 + w * 16;

    // Q fragments (pre-scaled), 8 k-tiles of m16k8
    unsigned qa[8][4];
#pragma unroll
    for (int kt = 0; kt < 8; kt++) {
        int c0 = kt * 8 + t4;
        qa[kt][0] = f2tf(Qg[(size_t)(q0 + g)     * HDIM + c0]     * ATT_SCALE);
        qa[kt][1] = f2tf(Qg[(size_t)(q0 + g + 8) * HDIM + c0]     * ATT_SCALE);
        qa[kt][2] = f2tf(Qg[(size_t)(q0 + g)     * HDIM + c0 + 4] * ATT_SCALE);
        qa[kt][3] = f2tf(Qg[(size_t)(q0 + g + 8) * HDIM + c0 + 4] * ATT_SCALE);
    }

    float o[8][4];
#pragma unroll
    for (int dt = 0; dt < 8; dt++)
        o[dt][0] = o[dt][1] = o[dt][2] = o[dt][3] = 0.0f;
    float mrow0 = -INFINITY, mrow1 = -INFINITY;
    float lrow0 = 0.0f, lrow1 = 0.0f;

    for (int j = 0; j < SEQ; j += 64) {
        __syncthreads();   // previous tile's P/V reads done before restaging
        // stage K,V tiles (tf32-rounded once at staging)
#pragma unroll
        for (int it = 0; it < 8; it++) {
            int lin = tid + it * 128;           // 0..1023
            int row = lin >> 4, q = lin & 15;
            float4 kv = *(const float4*)(Kg + (size_t)(j + row) * HDIM + q * 4);
            Ks[row][q * 4 + 0] = __uint_as_float(f2tf(kv.x));
            Ks[row][q * 4 + 1] = __uint_as_float(f2tf(kv.y));
            Ks[row][q * 4 + 2] = __uint_as_float(f2tf(kv.z));
            Ks[row][q * 4 + 3] = __uint_as_float(f2tf(kv.w));
            float4 vv = *(const float4*)(Vg + (size_t)(j + row) * HDIM + q * 4);
            Vs[row][q * 4 + 0] = __uint_as_float(f2tf(vv.x));
            Vs[row][q * 4 + 1] = __uint_as_float(f2tf(vv.y));
            Vs[row][q * 4 + 2] = __uint_as_float(f2tf(vv.z));
            Vs[row][q * 4 + 3] = __uint_as_float(f2tf(vv.w));
        }
        __syncthreads();

        // S = Qw (16x64) @ K^T (64x64)
        float s[8][4];
#pragma unroll
        for (int nt = 0; nt < 8; nt++)
            s[nt][0] = s[nt][1] = s[nt][2] = s[nt][3] = 0.0f;
#pragma unroll
        for (int kt = 0; kt < 8; kt++) {
#pragma unroll
            for (int nt = 0; nt < 8; nt++) {
                unsigned b0 = __float_as_uint(Ks[nt * 8 + g][kt * 8 + t4]);
                unsigned b1 = __float_as_uint(Ks[nt * 8 + g][kt * 8 + t4 + 4]);
                mma_tf32(s[nt], qa[kt], b0, b1);
            }
        }

        // online softmax (rows g and g+8; full row lives in the 4-lane group)
        float rm0 = -INFINITY, rm1 = -INFINITY;
#pragma unroll
        for (int nt = 0; nt < 8; nt++) {
            rm0 = fmaxf(rm0, fmaxf(s[nt][0], s[nt][1]));
            rm1 = fmaxf(rm1, fmaxf(s[nt][2], s[nt][3]));
        }
        rm0 = fmaxf(rm0, __shfl_xor_sync(0xffffffffu, rm0, 1));
        rm0 = fmaxf(rm0, __shfl_xor_sync(0xffffffffu, rm0, 2));
        rm1 = fmaxf(rm1, __shfl_xor_sync(0xffffffffu, rm1, 1));
        rm1 = fmaxf(rm1, __shfl_xor_sync(0xffffffffu, rm1, 2));

        float mn0 = fmaxf(mrow0, rm0);
        float mn1 = fmaxf(mrow1, rm1);
        float al0 = __expf(mrow0 - mn0);
        float al1 = __expf(mrow1 - mn1);

        float ps0 = 0.0f, ps1 = 0.0f;
#pragma unroll
        for (int nt = 0; nt < 8; nt++) {
            s[nt][0] = __expf(s[nt][0] - mn0);
            s[nt][1] = __expf(s[nt][1] - mn0);
            s[nt][2] = __expf(s[nt][2] - mn1);
            s[nt][3] = __expf(s[nt][3] - mn1);
            ps0 += s[nt][0] + s[nt][1];
            ps1 += s[nt][2] + s[nt][3];
        }
        ps0 += __shfl_xor_sync(0xffffffffu, ps0, 1);
        ps0 += __shfl_xor_sync(0xffffffffu, ps0, 2);
        ps1 += __shfl_xor_sync(0xffffffffu, ps1, 1);
        ps1 += __shfl_xor_sync(0xffffffffu, ps1, 2);

        lrow0 = lrow0 * al0 + ps0;  mrow0 = mn0;
        lrow1 = lrow1 * al1 + ps1;  mrow1 = mn1;

#pragma unroll
        for (int dt = 0; dt < 8; dt++) {
            o[dt][0] *= al0; o[dt][1] *= al0;
            o[dt][2] *= al1; o[dt][3] *= al1;
        }

        __syncthreads();   // all warps finished reading Ks -> safe to reuse as Ps
        // write P (tf32-rounded) into Ks region, rows w*16..w*16+15 (warp-private)
        const int pr0 = w * 16 + g, pr1 = w * 16 + g + 8;
#pragma unroll
        for (int nt = 0; nt < 8; nt++) {
            Ks[pr0][nt * 8 + 2 * t4]     = __uint_as_float(f2tf(s[nt][0]));
            Ks[pr0][nt * 8 + 2 * t4 + 1] = __uint_as_float(f2tf(s[nt][1]));
            Ks[pr1][nt * 8 + 2 * t4]     = __uint_as_float(f2tf(s[nt][2]));
            Ks[pr1][nt * 8 + 2 * t4 + 1] = __uint_as_float(f2tf(s[nt][3]));
        }
        __syncwarp();

        // O += P (16x64) @ V (64x64)
#pragma unroll
        for (int kt = 0; kt < 8; kt++) {
            unsigned pa[4];
            pa[0] = __float_as_uint(Ks[pr0][kt * 8 + t4]);
            pa[1] = __float_as_uint(Ks[pr1][kt * 8 + t4]);
            pa[2] = __float_as_uint(Ks[pr0][kt * 8 + t4 + 4]);
            pa[3] = __float_as_uint(Ks[pr1][kt * 8 + t4 + 4]);
#pragma unroll
            for (int dt = 0; dt < 8; dt++) {
                unsigned b0 = __float_as_uint(Vs[kt * 8 + t4][dt * 8 + g]);
                unsigned b1 = __float_as_uint(Vs[kt * 8 + t4 + 4][dt * 8 + g]);
                mma_tf32(o[dt], pa, b0, b1);
            }
        }
    }

    // epilogue: O/l -> g_AO in [B,N,H,Dh]
    const float il0 = 1.0f / lrow0;
    const float il1 = 1.0f / lrow1;
    const int b = bh >> 4, h = bh & 15;
    const int n0g = blockIdx.x * 64 + w * 16 + g;
    const size_t base0 = (((size_t)b * SEQ + n0g)     * NHEADS + h) * HDIM;
    const size_t base1 = (((size_t)b * SEQ + n0g + 8) * NHEADS + h) * HDIM;
#pragma unroll
    for (int dt = 0; dt < 8; dt++) {
        g_AO[base0 + dt * 8 + 2 * t4]     = o[dt][0] * il0;
        g_AO[base0 + dt * 8 + 2 * t4 + 1] = o[dt][1] * il0;
        g_AO[base1 + dt * 8 + 2 * t4]     = o[dt][2] * il1;
        g_AO[base1 + dt * 8 + 2 * t4 + 1] = o[dt][3] * il1;
    }
}

// bias add (per-column bias, row length 1024)
__global__ void bias_add_kernel(float* __restrict__ out,
                                const float* __restrict__ bias, int total)
{
    int i = blockIdx.x * blockDim.x + threadIdx.x;
    if (i < total) out[i] += bias[i & (DIMC - 1)];
}

extern "C" void kernel_launch(void* const* d_in, const int* in_sizes, int n_in,
                              void* d_out, int out_size)
{
    (void)in_sizes; (void)n_in; (void)out_size;
    const float* x     = (const float*)d_in[0];   // [4,2048,1024]
    const float* wqkv  = (const float*)d_in[1];   // [3072,1024]
    const float* wproj = (const float*)d_in[2];   // [1024,1024]
    const float* bproj = (const float*)d_in[3];   // [1024]
    float* out = (float*)d_out;                   // [4,2048,1024]

    // 1) QKV GEMM -> g_Q/g_K/g_V
    gemm_tf32_kernel<0><<<dim3(3 * DIMC / 128, MTOT / 128), 256>>>(
        x, wqkv, nullptr, MTOT, 3 * DIMC, DIMC);

    // 2) attention -> g_AO
    attn_kernel<<<dim3(SEQ / 64, BATCH * NHEADS), 128>>>();

    // 3) projection GEMM -> d_out (no bias yet)
    gemm_tf32_kernel<1><<<dim3(DIMC / 128, MTOT / 128), 256>>>(
        nullptr, wproj, out, MTOT, DIMC, DIMC);

    // 4) bias
    bias_add_kernel<<<(MTOT * DIMC + 255) / 256, 256>>>(out, bproj, MTOT * DIMC);
}

// round 6
// speedup vs baseline: 1.0666x; 1.0666x over previous
#include <cuda_runtime.h>
#include <cuda_bf16.h>
#include <mma.h>

using namespace nvcuda;

#define DIMC    1024
#define NHEADS  16
#define HDIM    64
#define BATCH   4
#define SEQ     2048
#define MTOT    (BATCH*SEQ)      // 8192
// scale folded with log2(e): softmax runs in base-2 domain
#define ATT_SCALE_LOG2E 0.180336880791190f   // (1/8) * log2(e)

// ---------------- scratch (static device globals; no allocation) ----------------
__device__ float g_Q[(size_t)BATCH*NHEADS*SEQ*HDIM];   // [B,H,N,Dh]
__device__ float g_K[(size_t)BATCH*NHEADS*SEQ*HDIM];
__device__ float g_V[(size_t)BATCH*NHEADS*SEQ*HDIM];
__device__ float g_AO[(size_t)MTOT*DIMC];              // [B,N,H,Dh] == [M, C]

// round-to-nearest fp32 -> tf32 (RNA is load-bearing: truncation biases dots ~1e-3)
__device__ __forceinline__ unsigned f2tf(float f) {
    unsigned u;
    asm("cvt.rna.tf32.f32 %0, %1;" : "=r"(u) : "f"(f));
    return u;
}

__device__ __forceinline__ void mma_tf32(float c[4], const unsigned a[4],
                                         unsigned b0, unsigned b1) {
    asm volatile(
        "mma.sync.aligned.m16n8k8.row.col.f32.tf32.tf32.f32 "
        "{%0,%1,%2,%3},{%4,%5,%6,%7},{%8,%9},{%0,%1,%2,%3};"
        : "+f"(c[0]), "+f"(c[1]), "+f"(c[2]), "+f"(c[3])
        : "r"(a[0]), "r"(a[1]), "r"(a[2]), "r"(a[3]), "r"(b0), "r"(b1));
}

// fast exp2 on the FMA pipe (valid for x <= ~0, clamped at -80).
// r = rne(x) via big-constant trick; 2^f by degree-4 Taylor (rel err <= ~6e-5);
// scale by 2^r via exponent-bit add. ~9 fma/alu ops vs MUFU rt=8cyc/SMSP.
__device__ __forceinline__ float fexp2(float x) {
    x = fmaxf(x, -80.0f);
    float t = x + 12582912.0f;            // 1.5*2^23: round-to-nearest-int
    int   i = __float_as_int(t);          // low bits hold the integer
    float r = t - 12582912.0f;
    float y = (x - r) * 0.6931471805599453f;   // f*ln2, f in [-0.5,0.5]
    float p = fmaf(y, 0.04166666667f, 0.16666666667f);
    p = fmaf(y, p, 0.5f);
    p = fmaf(y, p, 1.0f);
    p = fmaf(y, p, 1.0f);
    return __int_as_float(__float_as_int(p) + (i << 23));  // (i<<23) == r<<23 exactly
}

// ---------------- cp.async helpers ----------------
__device__ __forceinline__ void cp16(void* smem, const void* gmem) {
    unsigned s = (unsigned)__cvta_generic_to_shared(smem);
    asm volatile("cp.async.ca.shared.global [%0], [%1], 16;\n" :: "r"(s), "l"(gmem));
}
#define CP_COMMIT()  asm volatile("cp.async.commit_group;\n" ::: "memory")
#define CP_WAIT0()   asm volatile("cp.async.wait_group 0;\n" ::: "memory")
#define CP_WAIT1()   asm volatile("cp.async.wait_group 1;\n" ::: "memory")

// ================================================================================
// TF32 GEMM: C[M,N] = A[M,K] @ W[N,K]^T, 2-stage cp.async double-buffered.
// Block tile 128x128, BK=16 (BKP=20 keeps LDGSTS 16B-aligned: 80B rows), 8 warps.
// EPI==0: scatter into g_Q/g_K/g_V (qkv col j = t*1024 + h*64 + d)
// EPI==1: A is g_AO, store into Out row-major ld=N.
// ================================================================================
template<int EPI>
__global__ __launch_bounds__(256)
void gemm_tf32_kernel(const float* __restrict__ A_in,
                      const float* __restrict__ W,
                      float* __restrict__ Out,
                      int M, int N, int K)
{
    constexpr int BM = 128, BN = 128, BK = 16, BKP = 20;
    __shared__ float As[2][BM][BKP];
    __shared__ float Bs[2][BN][BKP];

    const float* A = (EPI == 1) ? (const float*)g_AO : A_in;

    const int tid = threadIdx.x;
    const int wid = tid >> 5;
    const int wm  = wid & 1;
    const int wn  = wid >> 1;
    const int m0  = blockIdx.y * BM;
    const int cn  = blockIdx.x * BN;

    // per-thread staging coords (each thread: 2 float4 of A, 2 of B per stage)
    const int r0 = tid >> 2,        q0 = tid & 3;         // lin = tid
    const int r1 = (tid + 256) >> 2, q1 = (tid + 256) & 3; // lin = tid+256

    wmma::fragment<wmma::accumulator, 16, 16, 8, float> acc[4][2];
#pragma unroll
    for (int mt = 0; mt < 4; mt++)
#pragma unroll
        for (int nt = 0; nt < 2; nt++)
            wmma::fill_fragment(acc[mt][nt], 0.0f);

    const int nk = K / BK;   // 64

    // prologue: stage 0
    cp16(&As[0][r0][q0 * 4], A + (size_t)(m0 + r0) * K + q0 * 4);
    cp16(&As[0][r1][q1 * 4], A + (size_t)(m0 + r1) * K + q1 * 4);
    cp16(&Bs[0][r0][q0 * 4], W + (size_t)(cn + r0) * K + q0 * 4);
    cp16(&Bs[0][r1][q1 * 4], W + (size_t)(cn + r1) * K + q1 * 4);
    CP_COMMIT();

    for (int kt = 0; kt < nk; kt++) {
        const int buf = kt & 1;
        if (kt + 1 < nk) {
            const int k0 = (kt + 1) * BK;
            cp16(&As[buf ^ 1][r0][q0 * 4], A + (size_t)(m0 + r0) * K + k0 + q0 * 4);
            cp16(&As[buf ^ 1][r1][q1 * 4], A + (size_t)(m0 + r1) * K + k0 + q1 * 4);
            cp16(&Bs[buf ^ 1][r0][q0 * 4], W + (size_t)(cn + r0) * K + k0 + q0 * 4);
            cp16(&Bs[buf ^ 1][r1][q1 * 4], W + (size_t)(cn + r1) * K + k0 + q1 * 4);
            CP_COMMIT();
            CP_WAIT1();
        } else {
            CP_WAIT0();
        }
        __syncthreads();

#pragma unroll
        for (int ks = 0; ks < BK; ks += 8) {
            wmma::fragment<wmma::matrix_a, 16, 16, 8, wmma::precision::tf32,
                           wmma::row_major> af[4];
            wmma::fragment<wmma::matrix_b, 16, 16, 8, wmma::precision::tf32,
                           wmma::col_major> bf[2];
#pragma unroll
            for (int mt = 0; mt < 4; mt++) {
                wmma::load_matrix_sync(af[mt], &As[buf][wm * 64 + mt * 16][ks], BKP);
#pragma unroll
                for (int i = 0; i < af[mt].num_elements; i++)
                    af[mt].x[i] = wmma::__float_to_tf32(af[mt].x[i]);
            }
#pragma unroll
            for (int nt = 0; nt < 2; nt++) {
                wmma::load_matrix_sync(bf[nt], &Bs[buf][wn * 32 + nt * 16][ks], BKP);
#pragma unroll
                for (int i = 0; i < bf[nt].num_elements; i++)
                    bf[nt].x[i] = wmma::__float_to_tf32(bf[nt].x[i]);
            }
#pragma unroll
            for (int mt = 0; mt < 4; mt++)
#pragma unroll
                for (int nt = 0; nt < 2; nt++)
                    wmma::mma_sync(acc[mt][nt], af[mt], bf[nt], acc[mt][nt]);
        }
        __syncthreads();
    }

#pragma unroll
    for (int mt = 0; mt < 4; mt++) {
#pragma unroll
        for (int nt = 0; nt < 2; nt++) {
            int j0 = cn + wn * 32 + nt * 16;
            int mg = m0 + wm * 64 + mt * 16;
            if (EPI == 0) {
                int t = j0 >> 10, r = j0 & 1023, h = r >> 6, d0 = r & 63;
                int b = mg >> 11, n0 = mg & 2047;
                float* base = (t == 0) ? g_Q : ((t == 1) ? g_K : g_V);
                wmma::store_matrix_sync(
                    base + (((size_t)(b * NHEADS + h) * SEQ + n0) * HDIM + d0),
                    acc[mt][nt], HDIM, wmma::mem_row_major);
            } else {
                wmma::store_matrix_sync(Out + (size_t)mg * N + j0,
                                        acc[mt][nt], N, wmma::mem_row_major);
            }
        }
    }
}

// ================================================================================
// Flash attention: grid (N/64, B*H), 128 threads (4 warps), each warp owns 16 q
// rows -> softmax fully warp-local. Scores kept in log2 domain (scale*log2e folded
// into Q); exp via FMA-pipe fexp2 (no MUFU). P repacked via smem (Ks reused).
// ================================================================================
__global__ __launch_bounds__(128)
void attn_kernel()
{
    __shared__ float Ks[64][68];   // keys x d ; reused as P (64 q-rows x 64 keys)
    __shared__ float Vs[64][72];   // keys x d

    const int tid = threadIdx.x;
    const int w   = tid >> 5;
    const int lane = tid & 31;
    const int g   = lane >> 2;
    const int t4  = lane & 3;

    const int bh = blockIdx.y;
    const float* Qg = g_Q + (size_t)bh * SEQ * HDIM;
    const float* Kg = g_K + (size_t)bh * SEQ * HDIM;
    const float* Vg = g_V + (size_t)bh * SEQ * HDIM;

    const int q0 = blockIdx.x * 64 + w * 16;

    unsigned qa[8][4];
#pragma unroll
    for (int kt = 0; kt < 8; kt++) {
        int c0 = kt * 8 + t4;
        qa[kt][0] = f2tf(Qg[(size_t)(q0 + g)     * HDIM + c0]     * ATT_SCALE_LOG2E);
        qa[kt][1] = f2tf(Qg[(size_t)(q0 + g + 8) * HDIM + c0]     * ATT_SCALE_LOG2E);
        qa[kt][2] = f2tf(Qg[(size_t)(q0 + g)     * HDIM + c0 + 4] * ATT_SCALE_LOG2E);
        qa[kt][3] = f2tf(Qg[(size_t)(q0 + g + 8) * HDIM + c0 + 4] * ATT_SCALE_LOG2E);
    }

    float o[8][4];
#pragma unroll
    for (int dt = 0; dt < 8; dt++)
        o[dt][0] = o[dt][1] = o[dt][2] = o[dt][3] = 0.0f;
    float mrow0 = -INFINITY, mrow1 = -INFINITY;
    float lrow0 = 0.0f, lrow1 = 0.0f;

    for (int j = 0; j < SEQ; j += 64) {
        __syncthreads();
#pragma unroll
        for (int it = 0; it < 8; it++) {
            int lin = tid + it * 128;
            int row = lin >> 4, q = lin & 15;
            float4 kv = *(const float4*)(Kg + (size_t)(j + row) * HDIM + q * 4);
            Ks[row][q * 4 + 0] = __uint_as_float(f2tf(kv.x));
            Ks[row][q * 4 + 1] = __uint_as_float(f2tf(kv.y));
            Ks[row][q * 4 + 2] = __uint_as_float(f2tf(kv.z));
            Ks[row][q * 4 + 3] = __uint_as_float(f2tf(kv.w));
            float4 vv = *(const float4*)(Vg + (size_t)(j + row) * HDIM + q * 4);
            Vs[row][q * 4 + 0] = __uint_as_float(f2tf(vv.x));
            Vs[row][q * 4 + 1] = __uint_as_float(f2tf(vv.y));
            Vs[row][q * 4 + 2] = __uint_as_float(f2tf(vv.z));
            Vs[row][q * 4 + 3] = __uint_as_float(f2tf(vv.w));
        }
        __syncthreads();

        // S (log2 domain) = Qw (16x64) @ K^T (64x64)
        float s[8][4];
#pragma unroll
        for (int nt = 0; nt < 8; nt++)
            s[nt][0] = s[nt][1] = s[nt][2] = s[nt][3] = 0.0f;
#pragma unroll
        for (int kt = 0; kt < 8; kt++) {
#pragma unroll
            for (int nt = 0; nt < 8; nt++) {
                unsigned b0 = __float_as_uint(Ks[nt * 8 + g][kt * 8 + t4]);
                unsigned b1 = __float_as_uint(Ks[nt * 8 + g][kt * 8 + t4 + 4]);
                mma_tf32(s[nt], qa[kt], b0, b1);
            }
        }

        // online softmax, base-2, fully FMA-pipe
        float rm0 = -INFINITY, rm1 = -INFINITY;
#pragma unroll
        for (int nt = 0; nt < 8; nt++) {
            rm0 = fmaxf(rm0, fmaxf(s[nt][0], s[nt][1]));
            rm1 = fmaxf(rm1, fmaxf(s[nt][2], s[nt][3]));
        }
        rm0 = fmaxf(rm0, __shfl_xor_sync(0xffffffffu, rm0, 1));
        rm0 = fmaxf(rm0, __shfl_xor_sync(0xffffffffu, rm0, 2));
        rm1 = fmaxf(rm1, __shfl_xor_sync(0xffffffffu, rm1, 1));
        rm1 = fmaxf(rm1, __shfl_xor_sync(0xffffffffu, rm1, 2));

        float mn0 = fmaxf(mrow0, rm0);
        float mn1 = fmaxf(mrow1, rm1);
        float al0 = fexp2(mrow0 - mn0);
        float al1 = fexp2(mrow1 - mn1);

        float ps0 = 0.0f, ps1 = 0.0f;
#pragma unroll
        for (int nt = 0; nt < 8; nt++) {
            s[nt][0] = fexp2(s[nt][0] - mn0);
            s[nt][1] = fexp2(s[nt][1] - mn0);
            s[nt][2] = fexp2(s[nt][2] - mn1);
            s[nt][3] = fexp2(s[nt][3] - mn1);
            ps0 += s[nt][0] + s[nt][1];
            ps1 += s[nt][2] + s[nt][3];
        }
        ps0 += __shfl_xor_sync(0xffffffffu, ps0, 1);
        ps0 += __shfl_xor_sync(0xffffffffu, ps0, 2);
        ps1 += __shfl_xor_sync(0xffffffffu, ps1, 1);
        ps1 += __shfl_xor_sync(0xffffffffu, ps1, 2);

        lrow0 = lrow0 * al0 + ps0;  mrow0 = mn0;
        lrow1 = lrow1 * al1 + ps1;  mrow1 = mn1;

#pragma unroll
        for (int dt = 0; dt < 8; dt++) {
            o[dt][0] *= al0; o[dt][1] *= al0;
            o[dt][2] *= al1; o[dt][3] *= al1;
        }

        __syncthreads();   // all warps done reading Ks -> reuse as P
        const int pr0 = w * 16 + g, pr1 = w * 16 + g + 8;
#pragma unroll
        for (int nt = 0; nt < 8; nt++) {
            Ks[pr0][nt * 8 + 2 * t4]     = __uint_as_float(f2tf(s[nt][0]));
            Ks[pr0][nt * 8 + 2 * t4 + 1] = __uint_as_float(f2tf(s[nt][1]));
            Ks[pr1][nt * 8 + 2 * t4]     = __uint_as_float(f2tf(s[nt][2]));
            Ks[pr1][nt * 8 + 2 * t4 + 1] = __uint_as_float(f2tf(s[nt][3]));
        }
        __syncwarp();

        // O += P (16x64) @ V (64x64)
#pragma unroll
        for (int kt = 0; kt < 8; kt++) {
            unsigned pa[4];
            pa[0] = __float_as_uint(Ks[pr0][kt * 8 + t4]);
            pa[1] = __float_as_uint(Ks[pr1][kt * 8 + t4]);
            pa[2] = __float_as_uint(Ks[pr0][kt * 8 + t4 + 4]);
            pa[3] = __float_as_uint(Ks[pr1][kt * 8 + t4 + 4]);
#pragma unroll
            for (int dt = 0; dt < 8; dt++) {
                unsigned b0 = __float_as_uint(Vs[kt * 8 + t4][dt * 8 + g]);
                unsigned b1 = __float_as_uint(Vs[kt * 8 + t4 + 4][dt * 8 + g]);
                mma_tf32(o[dt], pa, b0, b1);
            }
        }
    }

    const float il0 = 1.0f / lrow0;
    const float il1 = 1.0f / lrow1;
    const int b = bh >> 4, h = bh & 15;
    const int n0g = blockIdx.x * 64 + w * 16 + g;
    const size_t base0 = (((size_t)b * SEQ + n0g)     * NHEADS + h) * HDIM;
    const size_t base1 = (((size_t)b * SEQ + n0g + 8) * NHEADS + h) * HDIM;
#pragma unroll
    for (int dt = 0; dt < 8; dt++) {
        g_AO[base0 + dt * 8 + 2 * t4]     = o[dt][0] * il0;
        g_AO[base0 + dt * 8 + 2 * t4 + 1] = o[dt][1] * il0;
        g_AO[base1 + dt * 8 + 2 * t4]     = o[dt][2] * il1;
        g_AO[base1 + dt * 8 + 2 * t4 + 1] = o[dt][3] * il1;
    }
}

// vectorized bias add (row length 1024 floats = 256 float4)
__global__ void bias_add_kernel(float4* __restrict__ out,
                                const float* __restrict__ bias, int total4)
{
    int i = blockIdx.x * blockDim.x + threadIdx.x;
    if (i < total4) {
        int c = (i << 2) & (DIMC - 1);
        float4 v = out[i];
        v.x += __ldg(bias + c);
        v.y += __ldg(bias + c + 1);
        v.z += __ldg(bias + c + 2);
        v.w += __ldg(bias + c + 3);
        out[i] = v;
    }
}

extern "C" void kernel_launch(void* const* d_in, const int* in_sizes, int n_in,
                              void* d_out, int out_size)
{
    (void)in_sizes; (void)n_in; (void)out_size;
    const float* x     = (const float*)d_in[0];   // [4,2048,1024]
    const float* wqkv  = (const float*)d_in[1];   // [3072,1024]
    const float* wproj = (const float*)d_in[2];   // [1024,1024]
    const float* bproj = (const float*)d_in[3];   // [1024]
    float* out = (float*)d_out;                   // [4,2048,1024]

    gemm_tf32_kernel<0><<<dim3(3 * DIMC / 128, MTOT / 128), 256>>>(
        x, wqkv, nullptr, MTOT, 3 * DIMC, DIMC);

    attn_kernel<<<dim3(SEQ / 64, BATCH * NHEADS), 128>>>();

    gemm_tf32_kernel<1><<<dim3(DIMC / 128, MTOT / 128), 256>>>(
        nullptr, wproj, out, MTOT, DIMC, DIMC);

    bias_add_kernel<<<(MTOT * DIMC / 4 + 255) / 256, 256>>>(
        (float4*)out, bproj, MTOT * DIMC / 4);
}

// round 8
// speedup vs baseline: 1.1284x; 1.0579x over previous
#include <cuda_runtime.h>
#include <cuda_bf16.h>
#include <mma.h>

using namespace nvcuda;

#define DIMC    1024
#define NHEADS  16
#define HDIM    64
#define BATCH   4
#define SEQ     2048
#define MTOT    (BATCH*SEQ)      // 8192
// scale folded with log2(e): softmax runs in base-2 domain
#define ATT_SCALE_LOG2E 0.18033688011112042f   // (1/8) * log2(e)

// ---------------- scratch (static device globals; no allocation) ----------------
// Q stored pre-scaled by ATT_SCALE_LOG2E and RNA-rounded to tf32.
// K,V stored RNA-rounded to tf32 (attention mma sees exact tf32 bits).
__device__ float g_Q[(size_t)BATCH*NHEADS*SEQ*HDIM];   // [B,H,N,Dh]
__device__ float g_K[(size_t)BATCH*NHEADS*SEQ*HDIM];
__device__ float g_V[(size_t)BATCH*NHEADS*SEQ*HDIM];
__device__ float g_AO[(size_t)MTOT*DIMC];              // [B,N,H,Dh] == [M, C]

// round-to-nearest fp32 -> tf32 (RNA is load-bearing: truncation biases dots)
__device__ __forceinline__ unsigned f2tf(float f) {
    unsigned u;
    asm("cvt.rna.tf32.f32 %0, %1;" : "=r"(u) : "f"(f));
    return u;
}

__device__ __forceinline__ void mma_tf32(float c[4], const unsigned a[4],
                                         unsigned b0, unsigned b1) {
    asm volatile(
        "mma.sync.aligned.m16n8k8.row.col.f32.tf32.tf32.f32 "
        "{%0,%1,%2,%3},{%4,%5,%6,%7},{%8,%9},{%0,%1,%2,%3};"
        : "+f"(c[0]), "+f"(c[1]), "+f"(c[2]), "+f"(c[3])
        : "r"(a[0]), "r"(a[1]), "r"(a[2]), "r"(a[3]), "r"(b0), "r"(b1));
}

// fast exp2 on the FMA pipe (x <= 0, clamped at -80): rne split + deg-4 Taylor.
__device__ __forceinline__ float fexp2(float x) {
    x = fmaxf(x, -80.0f);
    float t = x + 12582912.0f;            // 1.5*2^23: round-to-nearest-int
    int   i = __float_as_int(t);
    float r = t - 12582912.0f;
    float y = (x - r) * 0.6931471805599453f;
    float p = fmaf(y, 0.04166666667f, 0.16666666667f);
    p = fmaf(y, p, 0.5f);
    p = fmaf(y, p, 1.0f);
    p = fmaf(y, p, 1.0f);
    return __int_as_float(__float_as_int(p) + (i << 23));
}

// ---------------- cp.async helpers ----------------
__device__ __forceinline__ void cp16(void* smem, const void* gmem) {
    unsigned s = (unsigned)__cvta_generic_to_shared(smem);
    asm volatile("cp.async.ca.shared.global [%0], [%1], 16;\n" :: "r"(s), "l"(gmem));
}
#define CP_COMMIT()  asm volatile("cp.async.commit_group;\n" ::: "memory")
#define CP_WAIT0()   asm volatile("cp.async.wait_group 0;\n" ::: "memory")
#define CP_WAIT1()   asm volatile("cp.async.wait_group 1;\n" ::: "memory")

// ================================================================================
// TF32 GEMM: C[M,N] = A[M,K] @ W[N,K]^T, 2-stage cp.async double-buffered.
// EPI==0: scatter into g_Q/g_K/g_V pre-rounded to tf32 (Q also pre-scaled)
// EPI==1: A is g_AO, store into Out row-major ld=N.
// ================================================================================
template<int EPI>
__global__ __launch_bounds__(256)
void gemm_tf32_kernel(const float* __restrict__ A_in,
                      const float* __restrict__ W,
                      float* __restrict__ Out,
                      int M, int N, int K)
{
    constexpr int BM = 128, BN = 128, BK = 16, BKP = 20;
    __shared__ float As[2][BM][BKP];
    __shared__ float Bs[2][BN][BKP];

    const float* A = (EPI == 1) ? (const float*)g_AO : A_in;

    const int tid = threadIdx.x;
    const int wid = tid >> 5;
    const int wm  = wid & 1;
    const int wn  = wid >> 1;
    const int m0  = blockIdx.y * BM;
    const int cn  = blockIdx.x * BN;

    const int r0 = tid >> 2,         q0 = tid & 3;
    const int r1 = (tid + 256) >> 2, q1 = (tid + 256) & 3;

    wmma::fragment<wmma::accumulator, 16, 16, 8, float> acc[4][2];
#pragma unroll
    for (int mt = 0; mt < 4; mt++)
#pragma unroll
        for (int nt = 0; nt < 2; nt++)
            wmma::fill_fragment(acc[mt][nt], 0.0f);

    const int nk = K / BK;

    cp16(&As[0][r0][q0 * 4], A + (size_t)(m0 + r0) * K + q0 * 4);
    cp16(&As[0][r1][q1 * 4], A + (size_t)(m0 + r1) * K + q1 * 4);
    cp16(&Bs[0][r0][q0 * 4], W + (size_t)(cn + r0) * K + q0 * 4);
    cp16(&Bs[0][r1][q1 * 4], W + (size_t)(cn + r1) * K + q1 * 4);
    CP_COMMIT();

    for (int kt = 0; kt < nk; kt++) {
        const int buf = kt & 1;
        if (kt + 1 < nk) {
            const int k0 = (kt + 1) * BK;
            cp16(&As[buf ^ 1][r0][q0 * 4], A + (size_t)(m0 + r0) * K + k0 + q0 * 4);
            cp16(&As[buf ^ 1][r1][q1 * 4], A + (size_t)(m0 + r1) * K + k0 + q1 * 4);
            cp16(&Bs[buf ^ 1][r0][q0 * 4], W + (size_t)(cn + r0) * K + k0 + q0 * 4);
            cp16(&Bs[buf ^ 1][r1][q1 * 4], W + (size_t)(cn + r1) * K + k0 + q1 * 4);
            CP_COMMIT();
            CP_WAIT1();
        } else {
            CP_WAIT0();
        }
        __syncthreads();

#pragma unroll
        for (int ks = 0; ks < BK; ks += 8) {
            wmma::fragment<wmma::matrix_a, 16, 16, 8, wmma::precision::tf32,
                           wmma::row_major> af[4];
            wmma::fragment<wmma::matrix_b, 16, 16, 8, wmma::precision::tf32,
                           wmma::col_major> bf[2];
#pragma unroll
            for (int mt = 0; mt < 4; mt++) {
                wmma::load_matrix_sync(af[mt], &As[buf][wm * 64 + mt * 16][ks], BKP);
#pragma unroll
                for (int i = 0; i < af[mt].num_elements; i++)
                    af[mt].x[i] = wmma::__float_to_tf32(af[mt].x[i]);
            }
#pragma unroll
            for (int nt = 0; nt < 2; nt++) {
                wmma::load_matrix_sync(bf[nt], &Bs[buf][wn * 32 + nt * 16][ks], BKP);
#pragma unroll
                for (int i = 0; i < bf[nt].num_elements; i++)
                    bf[nt].x[i] = wmma::__float_to_tf32(bf[nt].x[i]);
            }
#pragma unroll
            for (int mt = 0; mt < 4; mt++)
#pragma unroll
                for (int nt = 0; nt < 2; nt++)
                    wmma::mma_sync(acc[mt][nt], af[mt], bf[nt], acc[mt][nt]);
        }
        __syncthreads();
    }

#pragma unroll
    for (int mt = 0; mt < 4; mt++) {
#pragma unroll
        for (int nt = 0; nt < 2; nt++) {
            int j0 = cn + wn * 32 + nt * 16;
            int mg = m0 + wm * 64 + mt * 16;
            if (EPI == 0) {
                int t = j0 >> 10, r = j0 & 1023, h = r >> 6, d0 = r & 63;
                int b = mg >> 11, n0 = mg & 2047;
                float* base = (t == 0) ? g_Q : ((t == 1) ? g_K : g_V);
                const float mult = (t == 0) ? ATT_SCALE_LOG2E : 1.0f;
#pragma unroll
                for (int i = 0; i < acc[mt][nt].num_elements; i++)
                    acc[mt][nt].x[i] =
                        __uint_as_float(f2tf(acc[mt][nt].x[i] * mult));
                wmma::store_matrix_sync(
                    base + (((size_t)(b * NHEADS + h) * SEQ + n0) * HDIM + d0),
                    acc[mt][nt], HDIM, wmma::mem_row_major);
            } else {
                wmma::store_matrix_sync(Out + (size_t)mg * N + j0,
                                        acc[mt][nt], N, wmma::mem_row_major);
            }
        }
    }
}

// ================================================================================
// Flash attention v2: grid (N/128, B*H), 256 threads (8 warps, 16 q rows each).
// K/V tiles (exact tf32 bits) staged by cp.async, double buffered.
// P repack S-frag -> A-frag via intra-group shuffles (no smem P, no extra bar).
// ================================================================================
#define KS(b,r,c) sm[(((b)*64 + (r)) * 68) + (c)]
#define VS(b,r,c) sm[VOFF + (((b)*64 + (r)) * 72) + (c)]
#define VOFF (2*64*68)
#define ATT_SMEM_BYTES ((2*64*68 + 2*64*72) * 4)   // 71680 B

// stage one 64x64 K tile + one 64x64 V tile (256B/row = 16 chunks/row;
// 256 threads x 4 iters covers all 1024 chunks of each tile)
__device__ __forceinline__ void stage_kv(float* sm, int buf,
                                         const float* Kg, const float* Vg,
                                         int j, int tid)
{
#pragma unroll
    for (int it = 0; it < 4; it++) {
        int lin = tid + it * 256;          // 0..1023
        int row = lin >> 4, ch = lin & 15; // 64 rows x 16 chunks
        cp16(&KS(buf, row, ch * 4), Kg + (size_t)(j + row) * HDIM + ch * 4);
        cp16(&VS(buf, row, ch * 4), Vg + (size_t)(j + row) * HDIM + ch * 4);
    }
    CP_COMMIT();
}

__global__ __launch_bounds__(256)
void attn_kernel()
{
    extern __shared__ float sm[];

    const int tid  = threadIdx.x;
    const int w    = tid >> 5;
    const int lane = tid & 31;
    const int g    = lane >> 2;
    const int q    = lane & 3;

    const int bh = blockIdx.y;
    const float* Qg = g_Q + (size_t)bh * SEQ * HDIM;
    const float* Kg = g_K + (size_t)bh * SEQ * HDIM;
    const float* Vg = g_V + (size_t)bh * SEQ * HDIM;

    const int q0 = blockIdx.x * 128 + w * 16;

    // Q fragments: already scaled + tf32-rounded in GEMM epilogue
    unsigned qa[8][4];
#pragma unroll
    for (int kt = 0; kt < 8; kt++) {
        int c0 = kt * 8 + q;
        qa[kt][0] = __float_as_uint(Qg[(size_t)(q0 + g)     * HDIM + c0]);
        qa[kt][1] = __float_as_uint(Qg[(size_t)(q0 + g + 8) * HDIM + c0]);
        qa[kt][2] = __float_as_uint(Qg[(size_t)(q0 + g)     * HDIM + c0 + 4]);
        qa[kt][3] = __float_as_uint(Qg[(size_t)(q0 + g + 8) * HDIM + c0 + 4]);
    }

    float o[8][4];
#pragma unroll
    for (int dt = 0; dt < 8; dt++)
        o[dt][0] = o[dt][1] = o[dt][2] = o[dt][3] = 0.0f;
    float mrow0 = -INFINITY, mrow1 = -INFINITY;
    float lrow0 = 0.0f, lrow1 = 0.0f;

    // prologue: stage tiles 0 and 1
    stage_kv(sm, 0, Kg, Vg, 0,  tid);
    stage_kv(sm, 1, Kg, Vg, 64, tid);

    constexpr int NT = SEQ / 64;   // 32 tiles
    for (int t = 0; t < NT; t++) {
        const int buf = t & 1;
        if (t + 1 < NT) { CP_WAIT1(); } else { CP_WAIT0(); }
        __syncthreads();

        // S (log2 domain) = Qw (16x64) @ K^T (64x64)
        float s[8][4];
#pragma unroll
        for (int nt = 0; nt < 8; nt++)
            s[nt][0] = s[nt][1] = s[nt][2] = s[nt][3] = 0.0f;
#pragma unroll
        for (int kt = 0; kt < 8; kt++) {
#pragma unroll
            for (int nt = 0; nt < 8; nt++) {
                unsigned b0 = __float_as_uint(KS(buf, nt * 8 + g, kt * 8 + q));
                unsigned b1 = __float_as_uint(KS(buf, nt * 8 + g, kt * 8 + q + 4));
                mma_tf32(s[nt], qa[kt], b0, b1);
            }
        }

        // online softmax, base-2, FMA-pipe
        float rm0 = -INFINITY, rm1 = -INFINITY;
#pragma unroll
        for (int nt = 0; nt < 8; nt++) {
            rm0 = fmaxf(rm0, fmaxf(s[nt][0], s[nt][1]));
            rm1 = fmaxf(rm1, fmaxf(s[nt][2], s[nt][3]));
        }
        rm0 = fmaxf(rm0, __shfl_xor_sync(0xffffffffu, rm0, 1));
        rm0 = fmaxf(rm0, __shfl_xor_sync(0xffffffffu, rm0, 2));
        rm1 = fmaxf(rm1, __shfl_xor_sync(0xffffffffu, rm1, 1));
        rm1 = fmaxf(rm1, __shfl_xor_sync(0xffffffffu, rm1, 2));

        float mn0 = fmaxf(mrow0, rm0);
        float mn1 = fmaxf(mrow1, rm1);
        float al0 = fexp2(mrow0 - mn0);
        float al1 = fexp2(mrow1 - mn1);

        float ps0 = 0.0f, ps1 = 0.0f;
#pragma unroll
        for (int nt = 0; nt < 8; nt++) {
            s[nt][0] = fexp2(s[nt][0] - mn0);
            s[nt][1] = fexp2(s[nt][1] - mn0);
            s[nt][2] = fexp2(s[nt][2] - mn1);
            s[nt][3] = fexp2(s[nt][3] - mn1);
            ps0 += s[nt][0] + s[nt][1];
            ps1 += s[nt][2] + s[nt][3];
        }
        ps0 += __shfl_xor_sync(0xffffffffu, ps0, 1);
        ps0 += __shfl_xor_sync(0xffffffffu, ps0, 2);
        ps1 += __shfl_xor_sync(0xffffffffu, ps1, 1);
        ps1 += __shfl_xor_sync(0xffffffffu, ps1, 2);

        lrow0 = lrow0 * al0 + ps0;  mrow0 = mn0;
        lrow1 = lrow1 * al1 + ps1;  mrow1 = mn1;

#pragma unroll
        for (int dt = 0; dt < 8; dt++) {
            o[dt][0] *= al0; o[dt][1] *= al0;
            o[dt][2] *= al1; o[dt][3] *= al1;
        }

        // O += P (16x64) @ V (64x64); A-fragments gathered by intra-group shfl:
        // col q of A-frag lives in source lane (q>>1) of the S-frag, reg (q&1).
        const int srcA = (lane & ~3) | (q >> 1);
        const int srcB = srcA + 2;
        const bool odd = (q & 1);
#pragma unroll
        for (int kt = 0; kt < 8; kt++) {
            float u0 = __shfl_sync(0xffffffffu, s[kt][0], srcA);
            float u1 = __shfl_sync(0xffffffffu, s[kt][1], srcA);
            float u2 = __shfl_sync(0xffffffffu, s[kt][2], srcA);
            float u3 = __shfl_sync(0xffffffffu, s[kt][3], srcA);
            float v0 = __shfl_sync(0xffffffffu, s[kt][0], srcB);
            float v1 = __shfl_sync(0xffffffffu, s[kt][1], srcB);
            float v2 = __shfl_sync(0xffffffffu, s[kt][2], srcB);
            float v3 = __shfl_sync(0xffffffffu, s[kt][3], srcB);
            unsigned pa[4];
            pa[0] = f2tf(odd ? u1 : u0);
            pa[1] = f2tf(odd ? u3 : u2);
            pa[2] = f2tf(odd ? v1 : v0);
            pa[3] = f2tf(odd ? v3 : v2);
#pragma unroll
            for (int dt = 0; dt < 8; dt++) {
                unsigned b0 = __float_as_uint(VS(buf, kt * 8 + q,     dt * 8 + g));
                unsigned b1 = __float_as_uint(VS(buf, kt * 8 + q + 4, dt * 8 + g));
                mma_tf32(o[dt], pa, b0, b1);
            }
        }

        __syncthreads();   // all warps done reading buf before restaging it
        if (t + 2 < NT) {
            stage_kv(sm, buf, Kg, Vg, (t + 2) * 64, tid);
        }
    }

    const float il0 = 1.0f / lrow0;
    const float il1 = 1.0f / lrow1;
    const int b = bh >> 4, h = bh & 15;
    const int n0g = blockIdx.x * 128 + w * 16 + g;
    const size_t base0 = (((size_t)b * SEQ + n0g)     * NHEADS + h) * HDIM;
    const size_t base1 = (((size_t)b * SEQ + n0g + 8) * NHEADS + h) * HDIM;
#pragma unroll
    for (int dt = 0; dt < 8; dt++) {
        g_AO[base0 + dt * 8 + 2 * q]     = o[dt][0] * il0;
        g_AO[base0 + dt * 8 + 2 * q + 1] = o[dt][1] * il0;
        g_AO[base1 + dt * 8 + 2 * q]     = o[dt][2] * il1;
        g_AO[base1 + dt * 8 + 2 * q + 1] = o[dt][3] * il1;
    }
}

// vectorized bias add (row length 1024 floats = 256 float4)
__global__ void bias_add_kernel(float4* __restrict__ out,
                                const float* __restrict__ bias, int total4)
{
    int i = blockIdx.x * blockDim.x + threadIdx.x;
    if (i < total4) {
        int c = (i << 2) & (DIMC - 1);
        float4 v = out[i];
        v.x += __ldg(bias + c);
        v.y += __ldg(bias + c + 1);
        v.z += __ldg(bias + c + 2);
        v.w += __ldg(bias + c + 3);
        out[i] = v;
    }
}

extern "C" void kernel_launch(void* const* d_in, const int* in_sizes, int n_in,
                              void* d_out, int out_size)
{
    (void)in_sizes; (void)n_in; (void)out_size;
    const float* x     = (const float*)d_in[0];   // [4,2048,1024]
    const float* wqkv  = (const float*)d_in[1];   // [3072,1024]
    const float* wproj = (const float*)d_in[2];   // [1024,1024]
    const float* bproj = (const float*)d_in[3];   // [1024]
    float* out = (float*)d_out;                   // [4,2048,1024]

    // unconditional (no static guards per harness rules); cheap host-side call
    cudaFuncSetAttribute(attn_kernel,
                         cudaFuncAttributeMaxDynamicSharedMemorySize,
                         ATT_SMEM_BYTES);

    gemm_tf32_kernel<0><<<dim3(3 * DIMC / 128, MTOT / 128), 256>>>(
        x, wqkv, nullptr, MTOT, 3 * DIMC, DIMC);

    attn_kernel<<<dim3(SEQ / 128, BATCH * NHEADS), 256, ATT_SMEM_BYTES>>>();

    gemm_tf32_kernel<1><<<dim3(DIMC / 128, MTOT / 128), 256>>>(
        nullptr, wproj, out, MTOT, DIMC, DIMC);

    bias_add_kernel<<<(MTOT * DIMC / 4 + 255) / 256, 256>>>(
        (float4*)out, bproj, MTOT * DIMC / 4);
}

// round 10
// speedup vs baseline: 1.1384x; 1.0089x over previous
#include <cuda_runtime.h>
#include <cuda_bf16.h>
#include <mma.h>

using namespace nvcuda;

#define DIMC    1024
#define NHEADS  16
#define HDIM    64
#define BATCH   4
#define SEQ     2048
#define MTOT    (BATCH*SEQ)      // 8192
// scale folded with log2(e): softmax runs in base-2 domain
#define ATT_SCALE_LOG2E 0.18033688011112042f   // (1/8) * log2(e)

// ---------------- scratch (static device globals; no allocation) ----------------
// Q stored pre-scaled by ATT_SCALE_LOG2E and RNA-rounded to tf32.
// K,V stored RNA-rounded to tf32 (attention mma sees exact tf32 bits).
__device__ float g_Q[(size_t)BATCH*NHEADS*SEQ*HDIM];   // [B,H,N,Dh]
__device__ float g_K[(size_t)BATCH*NHEADS*SEQ*HDIM];
__device__ float g_V[(size_t)BATCH*NHEADS*SEQ*HDIM];
__device__ float g_AO[(size_t)MTOT*DIMC];              // [B,N,H,Dh] == [M, C]

// round-to-nearest fp32 -> tf32 (RNA is load-bearing: truncation biases dots)
__device__ __forceinline__ unsigned f2tf(float f) {
    unsigned u;
    asm("cvt.rna.tf32.f32 %0, %1;" : "=r"(u) : "f"(f));
    return u;
}

__device__ __forceinline__ void mma_tf32(float c[4], const unsigned a[4],
                                         unsigned b0, unsigned b1) {
    asm volatile(
        "mma.sync.aligned.m16n8k8.row.col.f32.tf32.tf32.f32 "
        "{%0,%1,%2,%3},{%4,%5,%6,%7},{%8,%9},{%0,%1,%2,%3};"
        : "+f"(c[0]), "+f"(c[1]), "+f"(c[2]), "+f"(c[3])
        : "r"(a[0]), "r"(a[1]), "r"(a[2]), "r"(a[3]), "r"(b0), "r"(b1));
}

// fast exp2 on the FMA pipe (x <= 0, clamped at -80): rne split + deg-4 Taylor.
__device__ __forceinline__ float fexp2(float x) {
    x = fmaxf(x, -80.0f);
    float t = x + 12582912.0f;            // 1.5*2^23: round-to-nearest-int
    int   i = __float_as_int(t);
    float r = t - 12582912.0f;
    float y = (x - r) * 0.6931471805599453f;
    float p = fmaf(y, 0.04166666667f, 0.16666666667f);
    p = fmaf(y, p, 0.5f);
    p = fmaf(y, p, 1.0f);
    p = fmaf(y, p, 1.0f);
    return __int_as_float(__float_as_int(p) + (i << 23));
}

// ---------------- cp.async helpers ----------------
__device__ __forceinline__ void cp16(void* smem, const void* gmem) {
    unsigned s = (unsigned)__cvta_generic_to_shared(smem);
    asm volatile("cp.async.ca.shared.global [%0], [%1], 16;\n" :: "r"(s), "l"(gmem));
}
#define CP_COMMIT()  asm volatile("cp.async.commit_group;\n" ::: "memory")
#define CP_WAIT0()   asm volatile("cp.async.wait_group 0;\n" ::: "memory")
#define CP_WAIT1()   asm volatile("cp.async.wait_group 1;\n" ::: "memory")

// ================================================================================
// TF32 GEMM: C[M,N] = A[M,K] @ W[N,K]^T, 2-stage cp.async double-buffered.
// EPI==0: scatter into g_Q/g_K/g_V pre-rounded to tf32 (Q also pre-scaled)
// EPI==1: A is g_AO, store into Out row-major ld=N.
// ================================================================================
template<int EPI>
__global__ __launch_bounds__(256)
void gemm_tf32_kernel(const float* __restrict__ A_in,
                      const float* __restrict__ W,
                      float* __restrict__ Out,
                      int M, int N, int K)
{
    constexpr int BM = 128, BN = 128, BK = 16, BKP = 20;
    __shared__ float As[2][BM][BKP];
    __shared__ float Bs[2][BN][BKP];

    const float* A = (EPI == 1) ? (const float*)g_AO : A_in;

    const int tid = threadIdx.x;
    const int wid = tid >> 5;
    const int wm  = wid & 1;
    const int wn  = wid >> 1;
    const int m0  = blockIdx.y * BM;
    const int cn  = blockIdx.x * BN;

    const int r0 = tid >> 2,         q0 = tid & 3;
    const int r1 = (tid + 256) >> 2, q1 = (tid + 256) & 3;

    wmma::fragment<wmma::accumulator, 16, 16, 8, float> acc[4][2];
#pragma unroll
    for (int mt = 0; mt < 4; mt++)
#pragma unroll
        for (int nt = 0; nt < 2; nt++)
            wmma::fill_fragment(acc[mt][nt], 0.0f);

    const int nk = K / BK;

    cp16(&As[0][r0][q0 * 4], A + (size_t)(m0 + r0) * K + q0 * 4);
    cp16(&As[0][r1][q1 * 4], A + (size_t)(m0 + r1) * K + q1 * 4);
    cp16(&Bs[0][r0][q0 * 4], W + (size_t)(cn + r0) * K + q0 * 4);
    cp16(&Bs[0][r1][q1 * 4], W + (size_t)(cn + r1) * K + q1 * 4);
    CP_COMMIT();

    for (int kt = 0; kt < nk; kt++) {
        const int buf = kt & 1;
        if (kt + 1 < nk) {
            const int k0 = (kt + 1) * BK;
            cp16(&As[buf ^ 1][r0][q0 * 4], A + (size_t)(m0 + r0) * K + k0 + q0 * 4);
            cp16(&As[buf ^ 1][r1][q1 * 4], A + (size_t)(m0 + r1) * K + k0 + q1 * 4);
            cp16(&Bs[buf ^ 1][r0][q0 * 4], W + (size_t)(cn + r0) * K + k0 + q0 * 4);
            cp16(&Bs[buf ^ 1][r1][q1 * 4], W + (size_t)(cn + r1) * K + k0 + q1 * 4);
            CP_COMMIT();
            CP_WAIT1();
        } else {
            CP_WAIT0();
        }
        __syncthreads();

#pragma unroll
        for (int ks = 0; ks < BK; ks += 8) {
            wmma::fragment<wmma::matrix_a, 16, 16, 8, wmma::precision::tf32,
                           wmma::row_major> af[4];
            wmma::fragment<wmma::matrix_b, 16, 16, 8, wmma::precision::tf32,
                           wmma::col_major> bf[2];
#pragma unroll
            for (int mt = 0; mt < 4; mt++) {
                wmma::load_matrix_sync(af[mt], &As[buf][wm * 64 + mt * 16][ks], BKP);
#pragma unroll
                for (int i = 0; i < af[mt].num_elements; i++)
                    af[mt].x[i] = wmma::__float_to_tf32(af[mt].x[i]);
            }
#pragma unroll
            for (int nt = 0; nt < 2; nt++) {
                wmma::load_matrix_sync(bf[nt], &Bs[buf][wn * 32 + nt * 16][ks], BKP);
#pragma unroll
                for (int i = 0; i < bf[nt].num_elements; i++)
                    bf[nt].x[i] = wmma::__float_to_tf32(bf[nt].x[i]);
            }
#pragma unroll
            for (int mt = 0; mt < 4; mt++)
#pragma unroll
                for (int nt = 0; nt < 2; nt++)
                    wmma::mma_sync(acc[mt][nt], af[mt], bf[nt], acc[mt][nt]);
        }
        __syncthreads();
    }

#pragma unroll
    for (int mt = 0; mt < 4; mt++) {
#pragma unroll
        for (int nt = 0; nt < 2; nt++) {
            int j0 = cn + wn * 32 + nt * 16;
            int mg = m0 + wm * 64 + mt * 16;
            if (EPI == 0) {
                int t = j0 >> 10, r = j0 & 1023, h = r >> 6, d0 = r & 63;
                int b = mg >> 11, n0 = mg & 2047;
                float* base = (t == 0) ? g_Q : ((t == 1) ? g_K : g_V);
                const float mult = (t == 0) ? ATT_SCALE_LOG2E : 1.0f;
#pragma unroll
                for (int i = 0; i < acc[mt][nt].num_elements; i++)
                    acc[mt][nt].x[i] =
                        __uint_as_float(f2tf(acc[mt][nt].x[i] * mult));
                wmma::store_matrix_sync(
                    base + (((size_t)(b * NHEADS + h) * SEQ + n0) * HDIM + d0),
                    acc[mt][nt], HDIM, wmma::mem_row_major);
            } else {
                wmma::store_matrix_sync(Out + (size_t)mg * N + j0,
                                        acc[mt][nt], N, wmma::mem_row_major);
            }
        }
    }
}

// ================================================================================
// Flash attention v3: grid (N/128, B*H), 256 threads (8 warps, 16 q rows each).
// K-tile shrunk to 32 keys: s[4][4] (-16 regs), half-size smem buffers so
// __launch_bounds__(256,2) gives 2 CTAs/SM (4 warps/SMSP) for latency hiding.
// ================================================================================
#define KT 32                      // keys per tile
#define KS(b,r,c) sm[(((b)*KT + (r)) * 68) + (c)]
#define VS(b,r,c) sm[VOFF + (((b)*KT + (r)) * 72) + (c)]
#define VOFF (2*KT*68)
#define ATT_SMEM_BYTES ((2*KT*68 + 2*KT*72) * 4)   // 35840 B

// stage one 32x64 K tile + one 32x64 V tile (16 chunks/row; 512 chunks each)
__device__ __forceinline__ void stage_kv(float* sm, int buf,
                                         const float* Kg, const float* Vg,
                                         int j, int tid)
{
#pragma unroll
    for (int it = 0; it < 2; it++) {
        int lin = tid + it * 256;          // 0..511
        int row = lin >> 4, ch = lin & 15; // 32 rows x 16 chunks
        cp16(&KS(buf, row, ch * 4), Kg + (size_t)(j + row) * HDIM + ch * 4);
        cp16(&VS(buf, row, ch * 4), Vg + (size_t)(j + row) * HDIM + ch * 4);
    }
    CP_COMMIT();
}

__global__ __launch_bounds__(256, 2)
void attn_kernel()
{
    extern __shared__ float sm[];

    const int tid  = threadIdx.x;
    const int w    = tid >> 5;
    const int lane = tid & 31;
    const int g    = lane >> 2;
    const int q    = lane & 3;

    const int bh = blockIdx.y;
    const float* Qg = g_Q + (size_t)bh * SEQ * HDIM;
    const float* Kg = g_K + (size_t)bh * SEQ * HDIM;
    const float* Vg = g_V + (size_t)bh * SEQ * HDIM;

    const int q0 = blockIdx.x * 128 + w * 16;

    // Q fragments: already scaled + tf32-rounded in GEMM epilogue
    unsigned qa[8][4];
#pragma unroll
    for (int kt = 0; kt < 8; kt++) {
        int c0 = kt * 8 + q;
        qa[kt][0] = __float_as_uint(Qg[(size_t)(q0 + g)     * HDIM + c0]);
        qa[kt][1] = __float_as_uint(Qg[(size_t)(q0 + g + 8) * HDIM + c0]);
        qa[kt][2] = __float_as_uint(Qg[(size_t)(q0 + g)     * HDIM + c0 + 4]);
        qa[kt][3] = __float_as_uint(Qg[(size_t)(q0 + g + 8) * HDIM + c0 + 4]);
    }

    float o[8][4];
#pragma unroll
    for (int dt = 0; dt < 8; dt++)
        o[dt][0] = o[dt][1] = o[dt][2] = o[dt][3] = 0.0f;
    float mrow0 = -INFINITY, mrow1 = -INFINITY;
    float lrow0 = 0.0f, lrow1 = 0.0f;

    // prologue: stage tiles 0 and 1
    stage_kv(sm, 0, Kg, Vg, 0,  tid);
    stage_kv(sm, 1, Kg, Vg, KT, tid);

    constexpr int NT = SEQ / KT;   // 64 tiles
    for (int t = 0; t < NT; t++) {
        const int buf = t & 1;
        if (t + 1 < NT) { CP_WAIT1(); } else { CP_WAIT0(); }
        __syncthreads();

        // S (log2 domain) = Qw (16x64) @ K^T (64x32)
        float s[4][4];
#pragma unroll
        for (int nt = 0; nt < 4; nt++)
            s[nt][0] = s[nt][1] = s[nt][2] = s[nt][3] = 0.0f;
#pragma unroll
        for (int kt = 0; kt < 8; kt++) {
#pragma unroll
            for (int nt = 0; nt < 4; nt++) {
                unsigned b0 = __float_as_uint(KS(buf, nt * 8 + g, kt * 8 + q));
                unsigned b1 = __float_as_uint(KS(buf, nt * 8 + g, kt * 8 + q + 4));
                mma_tf32(s[nt], qa[kt], b0, b1);
            }
        }

        // online softmax, base-2, FMA-pipe
        float rm0 = -INFINITY, rm1 = -INFINITY;
#pragma unroll
        for (int nt = 0; nt < 4; nt++) {
            rm0 = fmaxf(rm0, fmaxf(s[nt][0], s[nt][1]));
            rm1 = fmaxf(rm1, fmaxf(s[nt][2], s[nt][3]));
        }
        rm0 = fmaxf(rm0, __shfl_xor_sync(0xffffffffu, rm0, 1));
        rm0 = fmaxf(rm0, __shfl_xor_sync(0xffffffffu, rm0, 2));
        rm1 = fmaxf(rm1, __shfl_xor_sync(0xffffffffu, rm1, 1));
        rm1 = fmaxf(rm1, __shfl_xor_sync(0xffffffffu, rm1, 2));

        float mn0 = fmaxf(mrow0, rm0);
        float mn1 = fmaxf(mrow1, rm1);
        float al0 = fexp2(mrow0 - mn0);
        float al1 = fexp2(mrow1 - mn1);

        float ps0 = 0.0f, ps1 = 0.0f;
#pragma unroll
        for (int nt = 0; nt < 4; nt++) {
            s[nt][0] = fexp2(s[nt][0] - mn0);
            s[nt][1] = fexp2(s[nt][1] - mn0);
            s[nt][2] = fexp2(s[nt][2] - mn1);
            s[nt][3] = fexp2(s[nt][3] - mn1);
            ps0 += s[nt][0] + s[nt][1];
            ps1 += s[nt][2] + s[nt][3];
        }
        ps0 += __shfl_xor_sync(0xffffffffu, ps0, 1);
        ps0 += __shfl_xor_sync(0xffffffffu, ps0, 2);
        ps1 += __shfl_xor_sync(0xffffffffu, ps1, 1);
        ps1 += __shfl_xor_sync(0xffffffffu, ps1, 2);

        lrow0 = lrow0 * al0 + ps0;  mrow0 = mn0;
        lrow1 = lrow1 * al1 + ps1;  mrow1 = mn1;

#pragma unroll
        for (int dt = 0; dt < 8; dt++) {
            o[dt][0] *= al0; o[dt][1] *= al0;
            o[dt][2] *= al1; o[dt][3] *= al1;
        }

        // O += P (16x32) @ V (32x64); A-fragments gathered by intra-group shfl:
        // col q of A-frag lives in source lane (q>>1) of the S-frag, reg (q&1).
        const int srcA = (lane & ~3) | (q >> 1);
        const int srcB = srcA + 2;
        const bool odd = (q & 1);
#pragma unroll
        for (int kt = 0; kt < 4; kt++) {
            float u0 = __shfl_sync(0xffffffffu, s[kt][0], srcA);
            float u1 = __shfl_sync(0xffffffffu, s[kt][1], srcA);
            float u2 = __shfl_sync(0xffffffffu, s[kt][2], srcA);
            float u3 = __shfl_sync(0xffffffffu, s[kt][3], srcA);
            float v0 = __shfl_sync(0xffffffffu, s[kt][0], srcB);
            float v1 = __shfl_sync(0xffffffffu, s[kt][1], srcB);
            float v2 = __shfl_sync(0xffffffffu, s[kt][2], srcB);
            float v3 = __shfl_sync(0xffffffffu, s[kt][3], srcB);
            unsigned pa[4];
            pa[0] = f2tf(odd ? u1 : u0);
            pa[1] = f2tf(odd ? u3 : u2);
            pa[2] = f2tf(odd ? v1 : v0);
            pa[3] = f2tf(odd ? v3 : v2);
#pragma unroll
            for (int dt = 0; dt < 8; dt++) {
                unsigned b0 = __float_as_uint(VS(buf, kt * 8 + q,     dt * 8 + g));
                unsigned b1 = __float_as_uint(VS(buf, kt * 8 + q + 4, dt * 8 + g));
                mma_tf32(o[dt], pa, b0, b1);
            }
        }

        __syncthreads();   // all warps done reading buf before restaging it
        if (t + 2 < NT) {
            stage_kv(sm, buf, Kg, Vg, (t + 2) * KT, tid);
        }
    }

    const float il0 = 1.0f / lrow0;
    const float il1 = 1.0f / lrow1;
    const int b = bh >> 4, h = bh & 15;
    const int n0g = blockIdx.x * 128 + w * 16 + g;
    const size_t base0 = (((size_t)b * SEQ + n0g)     * NHEADS + h) * HDIM;
    const size_t base1 = (((size_t)b * SEQ + n0g + 8) * NHEADS + h) * HDIM;
#pragma unroll
    for (int dt = 0; dt < 8; dt++) {
        g_AO[base0 + dt * 8 + 2 * q]     = o[dt][0] * il0;
        g_AO[base0 + dt * 8 + 2 * q + 1] = o[dt][1] * il0;
        g_AO[base1 + dt * 8 + 2 * q]     = o[dt][2] * il1;
        g_AO[base1 + dt * 8 + 2 * q + 1] = o[dt][3] * il1;
    }
}

// vectorized bias add (row length 1024 floats = 256 float4)
__global__ void bias_add_kernel(float4* __restrict__ out,
                                const float* __restrict__ bias, int total4)
{
    int i = blockIdx.x * blockDim.x + threadIdx.x;
    if (i < total4) {
        int c = (i << 2) & (DIMC - 1);
        float4 v = out[i];
        v.x += __ldg(bias + c);
        v.y += __ldg(bias + c + 1);
        v.z += __ldg(bias + c + 2);
        v.w += __ldg(bias + c + 3);
        out[i] = v;
    }
}

extern "C" void kernel_launch(void* const* d_in, const int* in_sizes, int n_in,
                              void* d_out, int out_size)
{
    (void)in_sizes; (void)n_in; (void)out_size;
    const float* x     = (const float*)d_in[0];   // [4,2048,1024]
    const float* wqkv  = (const float*)d_in[1];   // [3072,1024]
    const float* wproj = (const float*)d_in[2];   // [1024,1024]
    const float* bproj = (const float*)d_in[3];   // [1024]
    float* out = (float*)d_out;                   // [4,2048,1024]

    cudaFuncSetAttribute(attn_kernel,
                         cudaFuncAttributeMaxDynamicSharedMemorySize,
                         ATT_SMEM_BYTES);

    gemm_tf32_kernel<0><<<dim3(3 * DIMC / 128, MTOT / 128), 256>>>(
        x, wqkv, nullptr, MTOT, 3 * DIMC, DIMC);

    attn_kernel<<<dim3(SEQ / 128, BATCH * NHEADS), 256, ATT_SMEM_BYTES>>>();

    gemm_tf32_kernel<1><<<dim3(DIMC / 128, MTOT / 128), 256>>>(
        nullptr, wproj, out, MTOT, DIMC, DIMC);

    bias_add_kernel<<<(MTOT * DIMC / 4 + 255) / 256, 256>>>(
        (float4*)out, bproj, MTOT * DIMC / 4);
}

// round 13
// speedup vs baseline: 1.3147x; 1.1549x over previous
#include <cstdint>
#include <stdint.h>
#include <cuda_runtime.h>
#include <cuda_bf16.h>
#include <mma.h>

using namespace nvcuda;

#define DIMC    1024
#define NHEADS  16
#define HDIM    64
#define BATCH   4
#define SEQ     2048
#define MTOT    (BATCH*SEQ)      // 8192
// scale folded with log2(e): softmax runs in base-2 domain
#define ATT_SCALE_LOG2E 0.18033688011112042f   // (1/8) * log2(e)

// ---------------- scratch (static device globals; no allocation) ----------------
// Q stored pre-scaled by ATT_SCALE_LOG2E and RNA-rounded to tf32.
// K,V stored RNA-rounded to tf32. g_AO stored RNA-rounded to tf32 (proj A operand).
__device__ float g_Q[(size_t)BATCH*NHEADS*SEQ*HDIM];   // [B,H,N,Dh]
__device__ float g_K[(size_t)BATCH*NHEADS*SEQ*HDIM];
__device__ float g_V[(size_t)BATCH*NHEADS*SEQ*HDIM];
__device__ float g_AO[(size_t)MTOT*DIMC];              // [B,N,H,Dh] == [M, C]
// tf32-pre-rounded GEMM operands (fp32 containers holding tf32 bit patterns)
__device__ float g_Xt [(size_t)MTOT*DIMC];             // x rounded
__device__ float g_Wqt[(size_t)3*DIMC*DIMC];           // w_qkv rounded
__device__ float g_Wpt[(size_t)DIMC*DIMC];             // w_proj rounded

// round-to-nearest fp32 -> tf32 (RNA is load-bearing: truncation biases dots)
__device__ __forceinline__ unsigned f2tf(float f) {
    unsigned u;
    asm("cvt.rna.tf32.f32 %0, %1;" : "=r"(u) : "f"(f));
    return u;
}

__device__ __forceinline__ void mma_tf32(float c[4], const unsigned a[4],
                                         unsigned b0, unsigned b1) {
    asm volatile(
        "mma.sync.aligned.m16n8k8.row.col.f32.tf32.tf32.f32 "
        "{%0,%1,%2,%3},{%4,%5,%6,%7},{%8,%9},{%0,%1,%2,%3};"
        : "+f"(c[0]), "+f"(c[1]), "+f"(c[2]), "+f"(c[3])
        : "r"(a[0]), "r"(a[1]), "r"(a[2]), "r"(a[3]), "r"(b0), "r"(b1));
}

// fast exp2 on the FMA pipe (x <= 0, clamped at -80); fexp2(0) == 1.0f exactly
__device__ __forceinline__ float fexp2(float x) {
    x = fmaxf(x, -80.0f);
    float t = x + 12582912.0f;            // 1.5*2^23: round-to-nearest-int
    int   i = __float_as_int(t);
    float r = t - 12582912.0f;
    float y = (x - r) * 0.6931471805599453f;
    float p = fmaf(y, 0.04166666667f, 0.16666666667f);
    p = fmaf(y, p, 0.5f);
    p = fmaf(y, p, 1.0f);
    p = fmaf(y, p, 1.0f);
    return __int_as_float(__float_as_int(p) + (i << 23));
}

// ---------------- cp.async helpers ----------------
__device__ __forceinline__ void cp16(void* smem, const void* gmem) {
    unsigned s = (unsigned)__cvta_generic_to_shared(smem);
    asm volatile("cp.async.ca.shared.global [%0], [%1], 16;\n" :: "r"(s), "l"(gmem));
}
#define CP_COMMIT()  asm volatile("cp.async.commit_group;\n" ::: "memory")
#define CP_WAIT0()   asm volatile("cp.async.wait_group 0;\n" ::: "memory")
#define CP_WAIT1()   asm volatile("cp.async.wait_group 1;\n" ::: "memory")

// ================================================================================
// prepass: round fp32 -> tf32 bit pattern (keeps fp32 container)
// ================================================================================
__global__ void round_tf32_kernel(const float4* __restrict__ in,
                                  float4* __restrict__ out, int n4)
{
    int i = blockIdx.x * blockDim.x + threadIdx.x;
    if (i >= n4) return;
    float4 v = in[i];
    v.x = __uint_as_float(f2tf(v.x));
    v.y = __uint_as_float(f2tf(v.y));
    v.z = __uint_as_float(f2tf(v.z));
    v.w = __uint_as_float(f2tf(v.w));
    out[i] = v;
}

// ================================================================================
// TF32 GEMM: C[M,N] = A[M,K] @ W[N,K]^T, 2-stage cp.async double-buffered.
// Inputs are PRE-ROUNDED to tf32 bits -> no cvt loops in the mainloop.
// EPI==0: scatter into g_Q/g_K/g_V (qkv col j = t*1024 + h*64 + d), Q pre-scaled.
// EPI==1: A is g_AO (pre-rounded by attn epilogue), store into Out row-major.
// ================================================================================
template<int EPI>
__global__ __launch_bounds__(256)
void gemm_tf32_kernel(const float* __restrict__ A_in,
                      const float* __restrict__ W,
                      float* __restrict__ Out,
                      int M, int N, int K)
{
    constexpr int BM = 128, BN = 128, BK = 16, BKP = 20;
    __shared__ float As[2][BM][BKP];
    __shared__ float Bs[2][BN][BKP];

    const float* A = (EPI == 1) ? (const float*)g_AO : A_in;

    const int tid = threadIdx.x;
    const int wid = tid >> 5;
    const int wm  = wid & 1;
    const int wn  = wid >> 1;
    const int m0  = blockIdx.y * BM;
    const int cn  = blockIdx.x * BN;

    const int r0 = tid >> 2,         q0 = tid & 3;
    const int r1 = (tid + 256) >> 2, q1 = (tid + 256) & 3;

    wmma::fragment<wmma::accumulator, 16, 16, 8, float> acc[4][2];
#pragma unroll
    for (int mt = 0; mt < 4; mt++)
#pragma unroll
        for (int nt = 0; nt < 2; nt++)
            wmma::fill_fragment(acc[mt][nt], 0.0f);

    const int nk = K / BK;

    cp16(&As[0][r0][q0 * 4], A + (size_t)(m0 + r0) * K + q0 * 4);
    cp16(&As[0][r1][q1 * 4], A + (size_t)(m0 + r1) * K + q1 * 4);
    cp16(&Bs[0][r0][q0 * 4], W + (size_t)(cn + r0) * K + q0 * 4);
    cp16(&Bs[0][r1][q1 * 4], W + (size_t)(cn + r1) * K + q1 * 4);
    CP_COMMIT();

    for (int kt = 0; kt < nk; kt++) {
        const int buf = kt & 1;
        if (kt + 1 < nk) {
            const int k0 = (kt + 1) * BK;
            cp16(&As[buf ^ 1][r0][q0 * 4], A + (size_t)(m0 + r0) * K + k0 + q0 * 4);
            cp16(&As[buf ^ 1][r1][q1 * 4], A + (size_t)(m0 + r1) * K + k0 + q1 * 4);
            cp16(&Bs[buf ^ 1][r0][q0 * 4], W + (size_t)(cn + r0) * K + k0 + q0 * 4);
            cp16(&Bs[buf ^ 1][r1][q1 * 4], W + (size_t)(cn + r1) * K + k0 + q1 * 4);
            CP_COMMIT();
            CP_WAIT1();
        } else {
            CP_WAIT0();
        }
        __syncthreads();

#pragma unroll
        for (int ks = 0; ks < BK; ks += 8) {
            wmma::fragment<wmma::matrix_a, 16, 16, 8, wmma::precision::tf32,
                           wmma::row_major> af[4];
            wmma::fragment<wmma::matrix_b, 16, 16, 8, wmma::precision::tf32,
                           wmma::col_major> bf[2];
            // operands already hold exact tf32 bit patterns: no cvt needed
#pragma unroll
            for (int mt = 0; mt < 4; mt++)
                wmma::load_matrix_sync(af[mt], &As[buf][wm * 64 + mt * 16][ks], BKP);
#pragma unroll
            for (int nt = 0; nt < 2; nt++)
                wmma::load_matrix_sync(bf[nt], &Bs[buf][wn * 32 + nt * 16][ks], BKP);
#pragma unroll
            for (int mt = 0; mt < 4; mt++)
#pragma unroll
                for (int nt = 0; nt < 2; nt++)
                    wmma::mma_sync(acc[mt][nt], af[mt], bf[nt], acc[mt][nt]);
        }
        __syncthreads();
    }

#pragma unroll
    for (int mt = 0; mt < 4; mt++) {
#pragma unroll
        for (int nt = 0; nt < 2; nt++) {
            int j0 = cn + wn * 32 + nt * 16;
            int mg = m0 + wm * 64 + mt * 16;
            if (EPI == 0) {
                int t = j0 >> 10, r = j0 & 1023, h = r >> 6, d0 = r & 63;
                int b = mg >> 11, n0 = mg & 2047;
                float* base = (t == 0) ? g_Q : ((t == 1) ? g_K : g_V);
                const float mult = (t == 0) ? ATT_SCALE_LOG2E : 1.0f;
#pragma unroll
                for (int i = 0; i < acc[mt][nt].num_elements; i++)
                    acc[mt][nt].x[i] =
                        __uint_as_float(f2tf(acc[mt][nt].x[i] * mult));
                wmma::store_matrix_sync(
                    base + (((size_t)(b * NHEADS + h) * SEQ + n0) * HDIM + d0),
                    acc[mt][nt], HDIM, wmma::mem_row_major);
            } else {
                wmma::store_matrix_sync(Out + (size_t)mg * N + j0,
                                        acc[mt][nt], N, wmma::mem_row_major);
            }
        }
    }
}

// ================================================================================
// Flash attention: grid (N/128, B*H), 256 threads (8 warps, 16 q rows each),
// 2 CTAs/SM. KT=32 keys/tile, cp.async double buffered, shuffle P-repack.
// NEW: ballot-guarded rescale skip (skip O-rescale + al fexp2 when no row's
// running max changed this tile).
// ================================================================================
#define KT 32
#define KS(b,r,c) sm[(((b)*KT + (r)) * 68) + (c)]
#define VS(b,r,c) sm[VOFF + (((b)*KT + (r)) * 72) + (c)]
#define VOFF (2*KT*68)
#define ATT_SMEM_BYTES ((2*KT*68 + 2*KT*72) * 4)   // 35840 B

__device__ __forceinline__ void stage_kv(float* sm, int buf,
                                         const float* Kg, const float* Vg,
                                         int j, int tid)
{
#pragma unroll
    for (int it = 0; it < 2; it++) {
        int lin = tid + it * 256;
        int row = lin >> 4, ch = lin & 15;
        cp16(&KS(buf, row, ch * 4), Kg + (size_t)(j + row) * HDIM + ch * 4);
        cp16(&VS(buf, row, ch * 4), Vg + (size_t)(j + row) * HDIM + ch * 4);
    }
    CP_COMMIT();
}

__global__ __launch_bounds__(256, 2)
void attn_kernel()
{
    extern __shared__ float sm[];

    const int tid  = threadIdx.x;
    const int w    = tid >> 5;
    const int lane = tid & 31;
    const int g    = lane >> 2;
    const int q    = lane & 3;

    const int bh = blockIdx.y;
    const float* Qg = g_Q + (size_t)bh * SEQ * HDIM;
    const float* Kg = g_K + (size_t)bh * SEQ * HDIM;
    const float* Vg = g_V + (size_t)bh * SEQ * HDIM;

    const int q0 = blockIdx.x * 128 + w * 16;

    unsigned qa[8][4];
#pragma unroll
    for (int kt = 0; kt < 8; kt++) {
        int c0 = kt * 8 + q;
        qa[kt][0] = __float_as_uint(Qg[(size_t)(q0 + g)     * HDIM + c0]);
        qa[kt][1] = __float_as_uint(Qg[(size_t)(q0 + g + 8) * HDIM + c0]);
        qa[kt][2] = __float_as_uint(Qg[(size_t)(q0 + g)     * HDIM + c0 + 4]);
        qa[kt][3] = __float_as_uint(Qg[(size_t)(q0 + g + 8) * HDIM + c0 + 4]);
    }

    float o[8][4];
#pragma unroll
    for (int dt = 0; dt < 8; dt++)
        o[dt][0] = o[dt][1] = o[dt][2] = o[dt][3] = 0.0f;
    float mrow0 = -INFINITY, mrow1 = -INFINITY;
    float lrow0 = 0.0f, lrow1 = 0.0f;

    stage_kv(sm, 0, Kg, Vg, 0,  tid);
    stage_kv(sm, 1, Kg, Vg, KT, tid);

    constexpr int NT = SEQ / KT;
    for (int t = 0; t < NT; t++) {
        const int buf = t & 1;
        if (t + 1 < NT) { CP_WAIT1(); } else { CP_WAIT0(); }
        __syncthreads();

        float s[4][4];
#pragma unroll
        for (int nt = 0; nt < 4; nt++)
            s[nt][0] = s[nt][1] = s[nt][2] = s[nt][3] = 0.0f;
#pragma unroll
        for (int kt = 0; kt < 8; kt++) {
#pragma unroll
            for (int nt = 0; nt < 4; nt++) {
                unsigned b0 = __float_as_uint(KS(buf, nt * 8 + g, kt * 8 + q));
                unsigned b1 = __float_as_uint(KS(buf, nt * 8 + g, kt * 8 + q + 4));
                mma_tf32(s[nt], qa[kt], b0, b1);
            }
        }

        float rm0 = -INFINITY, rm1 = -INFINITY;
#pragma unroll
        for (int nt = 0; nt < 4; nt++) {
            rm0 = fmaxf(rm0, fmaxf(s[nt][0], s[nt][1]));
            rm1 = fmaxf(rm1, fmaxf(s[nt][2], s[nt][3]));
        }
        rm0 = fmaxf(rm0, __shfl_xor_sync(0xffffffffu, rm0, 1));
        rm0 = fmaxf(rm0, __shfl_xor_sync(0xffffffffu, rm0, 2));
        rm1 = fmaxf(rm1, __shfl_xor_sync(0xffffffffu, rm1, 1));
        rm1 = fmaxf(rm1, __shfl_xor_sync(0xffffffffu, rm1, 2));

        float mn0 = fmaxf(mrow0, rm0);
        float mn1 = fmaxf(mrow1, rm1);

        // rescale only if some row's running max actually changed
        bool chg = (mn0 > mrow0) || (mn1 > mrow1);
        if (__ballot_sync(0xffffffffu, chg)) {
            float al0 = fexp2(mrow0 - mn0);   // == 1.0f for unchanged rows
            float al1 = fexp2(mrow1 - mn1);
            lrow0 *= al0;
            lrow1 *= al1;
#pragma unroll
            for (int dt = 0; dt < 8; dt++) {
                o[dt][0] *= al0; o[dt][1] *= al0;
                o[dt][2] *= al1; o[dt][3] *= al1;
            }
            mrow0 = mn0;
            mrow1 = mn1;
        }

        float ps0 = 0.0f, ps1 = 0.0f;
#pragma unroll
        for (int nt = 0; nt < 4; nt++) {
            s[nt][0] = fexp2(s[nt][0] - mrow0);
            s[nt][1] = fexp2(s[nt][1] - mrow0);
            s[nt][2] = fexp2(s[nt][2] - mrow1);
            s[nt][3] = fexp2(s[nt][3] - mrow1);
            ps0 += s[nt][0] + s[nt][1];
            ps1 += s[nt][2] + s[nt][3];
        }
        ps0 += __shfl_xor_sync(0xffffffffu, ps0, 1);
        ps0 += __shfl_xor_sync(0xffffffffu, ps0, 2);
        ps1 += __shfl_xor_sync(0xffffffffu, ps1, 1);
        ps1 += __shfl_xor_sync(0xffffffffu, ps1, 2);

        lrow0 += ps0;
        lrow1 += ps1;

        // O += P (16x32) @ V (32x64); A-fragments gathered by intra-group shfl:
        // col q of A-frag lives in source lane (q>>1) of the S-frag, reg (q&1).
        const int srcA = (lane & ~3) | (q >> 1);
        const int srcB = srcA + 2;
        const bool odd = (q & 1);
#pragma unroll
        for (int kt = 0; kt < 4; kt++) {
            float u0 = __shfl_sync(0xffffffffu, s[kt][0], srcA);
            float u1 = __shfl_sync(0xffffffffu, s[kt][1], srcA);
            float u2 = __shfl_sync(0xffffffffu, s[kt][2], srcA);
            float u3 = __shfl_sync(0xffffffffu, s[kt][3], srcA);
            float v0 = __shfl_sync(0xffffffffu, s[kt][0], srcB);
            float v1 = __shfl_sync(0xffffffffu, s[kt][1], srcB);
            float v2 = __shfl_sync(0xffffffffu, s[kt][2], srcB);
            float v3 = __shfl_sync(0xffffffffu, s[kt][3], srcB);
            unsigned pa[4];
            pa[0] = f2tf(odd ? u1 : u0);
            pa[1] = f2tf(odd ? u3 : u2);
            pa[2] = f2tf(odd ? v1 : v0);
            pa[3] = f2tf(odd ? v3 : v2);
#pragma unroll
            for (int dt = 0; dt < 8; dt++) {
                unsigned b0 = __float_as_uint(VS(buf, kt * 8 + q,     dt * 8 + g));
                unsigned b1 = __float_as_uint(VS(buf, kt * 8 + q + 4, dt * 8 + g));
                mma_tf32(o[dt], pa, b0, b1);
            }
        }

        __syncthreads();
        if (t + 2 < NT) {
            stage_kv(sm, buf, Kg, Vg, (t + 2) * KT, tid);
        }
    }

    // epilogue: O/l -> g_AO [B,N,H,Dh], pre-rounded to tf32 for the proj GEMM
    const float il0 = 1.0f / lrow0;
    const float il1 = 1.0f / lrow1;
    const int b = bh >> 4, h = bh & 15;
    const int n0g = blockIdx.x * 128 + w * 16 + g;
    const size_t base0 = (((size_t)b * SEQ + n0g)     * NHEADS + h) * HDIM;
    const size_t base1 = (((size_t)b * SEQ + n0g + 8) * NHEADS + h) * HDIM;
#pragma unroll
    for (int dt = 0; dt < 8; dt++) {
        g_AO[base0 + dt * 8 + 2 * q]     = __uint_as_float(f2tf(o[dt][0] * il0));
        g_AO[base0 + dt * 8 + 2 * q + 1] = __uint_as_float(f2tf(o[dt][1] * il0));
        g_AO[base1 + dt * 8 + 2 * q]     = __uint_as_float(f2tf(o[dt][2] * il1));
        g_AO[base1 + dt * 8 + 2 * q + 1] = __uint_as_float(f2tf(o[dt][3] * il1));
    }
}

// vectorized bias add (row length 1024 floats = 256 float4)
__global__ void bias_add_kernel(float4* __restrict__ out,
                                const float* __restrict__ bias, int total4)
{
    int i = blockIdx.x * blockDim.x + threadIdx.x;
    if (i < total4) {
        int c = (i << 2) & (DIMC - 1);
        float4 v = out[i];
        v.x += __ldg(bias + c);
        v.y += __ldg(bias + c + 1);
        v.z += __ldg(bias + c + 2);
        v.w += __ldg(bias + c + 3);
        out[i] = v;
    }
}

extern "C" void kernel_launch(void* const* d_in, const int* in_sizes, int n_in,
                              void* d_out, int out_size)
{
    (void)in_sizes; (void)n_in; (void)out_size;
    const float* x     = (const float*)d_in[0];   // [4,2048,1024]
    const float* wqkv  = (const float*)d_in[1];   // [3072,1024]
    const float* wproj = (const float*)d_in[2];   // [1024,1024]
    const float* bproj = (const float*)d_in[3];   // [1024]
    float* out = (float*)d_out;                   // [4,2048,1024]

    cudaFuncSetAttribute(attn_kernel,
                         cudaFuncAttributeMaxDynamicSharedMemorySize,
                         ATT_SMEM_BYTES);

    float *xt, *wqt, *wpt;
    cudaGetSymbolAddress((void**)&xt,  g_Xt);
    cudaGetSymbolAddress((void**)&wqt, g_Wqt);
    cudaGetSymbolAddress((void**)&wpt, g_Wpt);

    // 1) pre-round GEMM inputs to tf32 bits (removes cvt from GEMM mainloops)
    round_tf32_kernel<<<(MTOT * DIMC / 4 + 255) / 256, 256>>>(
        (const float4*)x, (float4*)xt, MTOT * DIMC / 4);
    round_tf32_kernel<<<(3 * DIMC * DIMC / 4 + 255) / 256, 256>>>(
        (const float4*)wqkv, (float4*)wqt, 3 * DIMC * DIMC / 4);
    round_tf32_kernel<<<(DIMC * DIMC / 4 + 255) / 256, 256>>>(
        (const float4*)wproj, (float4*)wpt, DIMC * DIMC / 4);

    // 2) QKV GEMM -> g_Q/g_K/g_V (Q pre-scaled, all pre-rounded)
    gemm_tf32_kernel<0><<<dim3(3 * DIMC / 128, MTOT / 128), 256>>>(
        xt, wqt, nullptr, MTOT, 3 * DIMC, DIMC);

    // 3) attention -> g_AO (pre-rounded)
    attn_kernel<<<dim3(SEQ / 128, BATCH * NHEADS), 256, ATT_SMEM_BYTES>>>();

    // 4) projection GEMM -> out
    gemm_tf32_kernel<1><<<dim3(DIMC / 128, MTOT / 128), 256>>>(
        nullptr, wpt, out, MTOT, DIMC, DIMC);

    // 5) bias
    bias_add_kernel<<<(MTOT * DIMC / 4 + 255) / 256, 256>>>(
        (float4*)out, bproj, MTOT * DIMC / 4);
}

// round 14
// speedup vs baseline: 1.8034x; 1.3717x over previous
#include <cstdint>
#include <stdint.h>
#include <cuda_runtime.h>
#include <cuda_bf16.h>

#define DIMC    1024
#define NHEADS  16
#define HDIM    64
#define BATCH   4
#define SEQ     2048
#define MTOT    (BATCH*SEQ)      // 8192
// scale folded with log2(e): softmax runs in base-2 domain
#define ATT_SCALE_LOG2E 0.18033688011112042f   // (1/8) * log2(e)

// ---------------- scratch (static device globals; no allocation) ----------------
__device__ float g_Q[(size_t)BATCH*NHEADS*SEQ*HDIM];   // [B,H,N,Dh]
__device__ float g_K[(size_t)BATCH*NHEADS*SEQ*HDIM];
__device__ float g_V[(size_t)BATCH*NHEADS*SEQ*HDIM];
__device__ float g_AO[(size_t)MTOT*DIMC];              // [B,N,H,Dh] == [M, C]
// tf32-pre-rounded GEMM operands (fp32 containers holding tf32 bit patterns)
__device__ float g_Xt [(size_t)MTOT*DIMC];
__device__ float g_Wqt[(size_t)3*DIMC*DIMC];
__device__ float g_Wpt[(size_t)DIMC*DIMC];

// round-to-nearest fp32 -> tf32 (RNA is load-bearing)
__device__ __forceinline__ unsigned f2tf(float f) {
    unsigned u;
    asm("cvt.rna.tf32.f32 %0, %1;" : "=r"(u) : "f"(f));
    return u;
}

__device__ __forceinline__ void mma_tf32(float c[4], const unsigned a[4],
                                         unsigned b0, unsigned b1) {
    asm volatile(
        "mma.sync.aligned.m16n8k8.row.col.f32.tf32.tf32.f32 "
        "{%0,%1,%2,%3},{%4,%5,%6,%7},{%8,%9},{%0,%1,%2,%3};"
        : "+f"(c[0]), "+f"(c[1]), "+f"(c[2]), "+f"(c[3])
        : "r"(a[0]), "r"(a[1]), "r"(a[2]), "r"(a[3]), "r"(b0), "r"(b1));
}

// fast exp2 on the FMA pipe (x <= 0, clamped at -80); fexp2(0) == 1.0f exactly
__device__ __forceinline__ float fexp2(float x) {
    x = fmaxf(x, -80.0f);
    float t = x + 12582912.0f;
    int   i = __float_as_int(t);
    float r = t - 12582912.0f;
    float y = (x - r) * 0.6931471805599453f;
    float p = fmaf(y, 0.04166666667f, 0.16666666667f);
    p = fmaf(y, p, 0.5f);
    p = fmaf(y, p, 1.0f);
    p = fmaf(y, p, 1.0f);
    return __int_as_float(__float_as_int(p) + (i << 23));
}

// ---------------- cp.async helpers ----------------
__device__ __forceinline__ void cp16(void* smem, const void* gmem) {
    unsigned s = (unsigned)__cvta_generic_to_shared(smem);
    asm volatile("cp.async.ca.shared.global [%0], [%1], 16;\n" :: "r"(s), "l"(gmem));
}
#define CP_COMMIT()  asm volatile("cp.async.commit_group;\n" ::: "memory")
#define CP_WAIT0()   asm volatile("cp.async.wait_group 0;\n" ::: "memory")
#define CP_WAIT1()   asm volatile("cp.async.wait_group 1;\n" ::: "memory")

// ================================================================================
// prepass: round fp32 -> tf32 bit pattern (keeps fp32 container)
// ================================================================================
__global__ void round_tf32_kernel(const float4* __restrict__ in,
                                  float4* __restrict__ out, int n4)
{
    int i = blockIdx.x * blockDim.x + threadIdx.x;
    if (i >= n4) return;
    float4 v = in[i];
    v.x = __uint_as_float(f2tf(v.x));
    v.y = __uint_as_float(f2tf(v.y));
    v.z = __uint_as_float(f2tf(v.z));
    v.w = __uint_as_float(f2tf(v.w));
    out[i] = v;
}

// ================================================================================
// Raw-PTX TF32 GEMM: C[M,N] = A[M,K] @ W[N,K]^T, 2-stage cp.async.
// Block 128x128, BK=16, 8 warps (2m x 4n), warp tile 64x32 as 4m x 4n m16n8k8.
// Mainloop: load ALL 16 fragments (48 LDS, conflict-free: lane->bank bijective
// under BKP=20), then issue all 32 HMMA back-to-back (pipelinable chain).
// EPI==0: scatter to g_Q/g_K/g_V (tf32 pre-round, Q pre-scaled), float2 stores.
// EPI==1: A = g_AO, C -> Out row-major, float2 stores.
// ================================================================================
template<int EPI>
__global__ __launch_bounds__(256, 2)
void gemm_tf32_kernel(const float* __restrict__ A_in,
                      const float* __restrict__ W,
                      float* __restrict__ Out,
                      int M, int N, int K)
{
    constexpr int BM = 128, BN = 128, BK = 16, BKP = 20;
    __shared__ float As[2][BM][BKP];
    __shared__ float Bs[2][BN][BKP];

    const float* A = (EPI == 1) ? (const float*)g_AO : A_in;

    const int tid  = threadIdx.x;
    const int wid  = tid >> 5;
    const int lane = tid & 31;
    const int g    = lane >> 2;
    const int q    = lane & 3;
    const int wm   = wid & 1;
    const int wn   = wid >> 1;
    const int m0   = blockIdx.y * BM;
    const int cn   = blockIdx.x * BN;

    const int r0 = tid >> 2,         q0 = tid & 3;
    const int r1 = (tid + 256) >> 2, q1 = (tid + 256) & 3;

    float acc[4][4][4];
#pragma unroll
    for (int mt = 0; mt < 4; mt++)
#pragma unroll
        for (int nt = 0; nt < 4; nt++)
            acc[mt][nt][0] = acc[mt][nt][1] = acc[mt][nt][2] = acc[mt][nt][3] = 0.0f;

    const int nk = K / BK;

    cp16(&As[0][r0][q0 * 4], A + (size_t)(m0 + r0) * K + q0 * 4);
    cp16(&As[0][r1][q1 * 4], A + (size_t)(m0 + r1) * K + q1 * 4);
    cp16(&Bs[0][r0][q0 * 4], W + (size_t)(cn + r0) * K + q0 * 4);
    cp16(&Bs[0][r1][q1 * 4], W + (size_t)(cn + r1) * K + q1 * 4);
    CP_COMMIT();

    for (int kt = 0; kt < nk; kt++) {
        const int buf = kt & 1;
        if (kt + 1 < nk) {
            const int k0 = (kt + 1) * BK;
            cp16(&As[buf ^ 1][r0][q0 * 4], A + (size_t)(m0 + r0) * K + k0 + q0 * 4);
            cp16(&As[buf ^ 1][r1][q1 * 4], A + (size_t)(m0 + r1) * K + k0 + q1 * 4);
            cp16(&Bs[buf ^ 1][r0][q0 * 4], W + (size_t)(cn + r0) * K + k0 + q0 * 4);
            cp16(&Bs[buf ^ 1][r1][q1 * 4], W + (size_t)(cn + r1) * K + k0 + q1 * 4);
            CP_COMMIT();
            CP_WAIT1();
        } else {
            CP_WAIT0();
        }
        __syncthreads();

        // load all fragments for BK=16 (2 k8-steps)
        unsigned a[2][4][4];
        unsigned b[2][4][2];
#pragma unroll
        for (int ks = 0; ks < 2; ks++) {
#pragma unroll
            for (int mt = 0; mt < 4; mt++) {
                const int row = wm * 64 + mt * 16;
                a[ks][mt][0] = __float_as_uint(As[buf][row + g    ][ks * 8 + q    ]);
                a[ks][mt][1] = __float_as_uint(As[buf][row + g + 8][ks * 8 + q    ]);
                a[ks][mt][2] = __float_as_uint(As[buf][row + g    ][ks * 8 + q + 4]);
                a[ks][mt][3] = __float_as_uint(As[buf][row + g + 8][ks * 8 + q + 4]);
            }
#pragma unroll
            for (int nt = 0; nt < 4; nt++) {
                const int col = wn * 32 + nt * 8;
                b[ks][nt][0] = __float_as_uint(Bs[buf][col + g][ks * 8 + q    ]);
                b[ks][nt][1] = __float_as_uint(Bs[buf][col + g][ks * 8 + q + 4]);
            }
        }
        // issue all 32 HMMA back-to-back
#pragma unroll
        for (int ks = 0; ks < 2; ks++)
#pragma unroll
            for (int mt = 0; mt < 4; mt++)
#pragma unroll
                for (int nt = 0; nt < 4; nt++)
                    mma_tf32(acc[mt][nt], a[ks][mt], b[ks][nt][0], b[ks][nt][1]);

        __syncthreads();
    }

    // epilogue: C layout per m16n8 acc: c0,c1 = (row g,   col 2q, 2q+1)
    //                                   c2,c3 = (row g+8, col 2q, 2q+1)
#pragma unroll
    for (int mt = 0; mt < 4; mt++) {
        const int row0 = m0 + wm * 64 + mt * 16 + g;
#pragma unroll
        for (int nt = 0; nt < 4; nt++) {
            const int j = cn + wn * 32 + nt * 8 + 2 * q;
            if (EPI == 0) {
                const int t = j >> 10, r = j & 1023, h = r >> 6, d = r & 63;
                const int bI = row0 >> 11, n0 = row0 & 2047;
                float* base = (t == 0) ? g_Q : ((t == 1) ? g_K : g_V);
                const float mult = (t == 0) ? ATT_SCALE_LOG2E : 1.0f;
                float* p0 = base + (((size_t)(bI * NHEADS + h) * SEQ + n0) * HDIM + d);
                float2 v0, v1;
                v0.x = __uint_as_float(f2tf(acc[mt][nt][0] * mult));
                v0.y = __uint_as_float(f2tf(acc[mt][nt][1] * mult));
                v1.x = __uint_as_float(f2tf(acc[mt][nt][2] * mult));
                v1.y = __uint_as_float(f2tf(acc[mt][nt][3] * mult));
                *reinterpret_cast<float2*>(p0) = v0;
                *reinterpret_cast<float2*>(p0 + 8 * HDIM) = v1;   // row0+8
            } else {
                float2 v0 = { acc[mt][nt][0], acc[mt][nt][1] };
                float2 v1 = { acc[mt][nt][2], acc[mt][nt][3] };
                *reinterpret_cast<float2*>(Out + (size_t)row0 * N + j) = v0;
                *reinterpret_cast<float2*>(Out + (size_t)(row0 + 8) * N + j) = v1;
            }
        }
    }
}

// ================================================================================
// Flash attention (unchanged from R13, passing): grid (N/128, B*H), 256 thr,
// 2 CTAs/SM, KT=32, cp.async double-buffered, shuffle P-repack, rescale skip.
// ================================================================================
#define KT 32
#define KS(b,r,c) sm[(((b)*KT + (r)) * 68) + (c)]
#define VS(b,r,c) sm[VOFF + (((b)*KT + (r)) * 72) + (c)]
#define VOFF (2*KT*68)
#define ATT_SMEM_BYTES ((2*KT*68 + 2*KT*72) * 4)   // 35840 B

__device__ __forceinline__ void stage_kv(float* sm, int buf,
                                         const float* Kg, const float* Vg,
                                         int j, int tid)
{
#pragma unroll
    for (int it = 0; it < 2; it++) {
        int lin = tid + it * 256;
        int row = lin >> 4, ch = lin & 15;
        cp16(&KS(buf, row, ch * 4), Kg + (size_t)(j + row) * HDIM + ch * 4);
        cp16(&VS(buf, row, ch * 4), Vg + (size_t)(j + row) * HDIM + ch * 4);
    }
    CP_COMMIT();
}

__global__ __launch_bounds__(256, 2)
void attn_kernel()
{
    extern __shared__ float sm[];

    const int tid  = threadIdx.x;
    const int w    = tid >> 5;
    const int lane = tid & 31;
    const int g    = lane >> 2;
    const int q    = lane & 3;

    const int bh = blockIdx.y;
    const float* Qg = g_Q + (size_t)bh * SEQ * HDIM;
    const float* Kg = g_K + (size_t)bh * SEQ * HDIM;
    const float* Vg = g_V + (size_t)bh * SEQ * HDIM;

    const int q0 = blockIdx.x * 128 + w * 16;

    unsigned qa[8][4];
#pragma unroll
    for (int kt = 0; kt < 8; kt++) {
        int c0 = kt * 8 + q;
        qa[kt][0] = __float_as_uint(Qg[(size_t)(q0 + g)     * HDIM + c0]);
        qa[kt][1] = __float_as_uint(Qg[(size_t)(q0 + g + 8) * HDIM + c0]);
        qa[kt][2] = __float_as_uint(Qg[(size_t)(q0 + g)     * HDIM + c0 + 4]);
        qa[kt][3] = __float_as_uint(Qg[(size_t)(q0 + g + 8) * HDIM + c0 + 4]);
    }

    float o[8][4];
#pragma unroll
    for (int dt = 0; dt < 8; dt++)
        o[dt][0] = o[dt][1] = o[dt][2] = o[dt][3] = 0.0f;
    float mrow0 = -INFINITY, mrow1 = -INFINITY;
    float lrow0 = 0.0f, lrow1 = 0.0f;

    stage_kv(sm, 0, Kg, Vg, 0,  tid);
    stage_kv(sm, 1, Kg, Vg, KT, tid);

    constexpr int NT = SEQ / KT;
    for (int t = 0; t < NT; t++) {
        const int buf = t & 1;
        if (t + 1 < NT) { CP_WAIT1(); } else { CP_WAIT0(); }
        __syncthreads();

        float s[4][4];
#pragma unroll
        for (int nt = 0; nt < 4; nt++)
            s[nt][0] = s[nt][1] = s[nt][2] = s[nt][3] = 0.0f;
#pragma unroll
        for (int kt = 0; kt < 8; kt++) {
#pragma unroll
            for (int nt = 0; nt < 4; nt++) {
                unsigned b0 = __float_as_uint(KS(buf, nt * 8 + g, kt * 8 + q));
                unsigned b1 = __float_as_uint(KS(buf, nt * 8 + g, kt * 8 + q + 4));
                mma_tf32(s[nt], qa[kt], b0, b1);
            }
        }

        float rm0 = -INFINITY, rm1 = -INFINITY;
#pragma unroll
        for (int nt = 0; nt < 4; nt++) {
            rm0 = fmaxf(rm0, fmaxf(s[nt][0], s[nt][1]));
            rm1 = fmaxf(rm1, fmaxf(s[nt][2], s[nt][3]));
        }
        rm0 = fmaxf(rm0, __shfl_xor_sync(0xffffffffu, rm0, 1));
        rm0 = fmaxf(rm0, __shfl_xor_sync(0xffffffffu, rm0, 2));
        rm1 = fmaxf(rm1, __shfl_xor_sync(0xffffffffu, rm1, 1));
        rm1 = fmaxf(rm1, __shfl_xor_sync(0xffffffffu, rm1, 2));

        float mn0 = fmaxf(mrow0, rm0);
        float mn1 = fmaxf(mrow1, rm1);

        bool chg = (mn0 > mrow0) || (mn1 > mrow1);
        if (__ballot_sync(0xffffffffu, chg)) {
            float al0 = fexp2(mrow0 - mn0);
            float al1 = fexp2(mrow1 - mn1);
            lrow0 *= al0;
            lrow1 *= al1;
#pragma unroll
            for (int dt = 0; dt < 8; dt++) {
                o[dt][0] *= al0; o[dt][1] *= al0;
                o[dt][2] *= al1; o[dt][3] *= al1;
            }
            mrow0 = mn0;
            mrow1 = mn1;
        }

        float ps0 = 0.0f, ps1 = 0.0f;
#pragma unroll
        for (int nt = 0; nt < 4; nt++) {
            s[nt][0] = fexp2(s[nt][0] - mrow0);
            s[nt][1] = fexp2(s[nt][1] - mrow0);
            s[nt][2] = fexp2(s[nt][2] - mrow1);
            s[nt][3] = fexp2(s[nt][3] - mrow1);
            ps0 += s[nt][0] + s[nt][1];
            ps1 += s[nt][2] + s[nt][3];
        }
        ps0 += __shfl_xor_sync(0xffffffffu, ps0, 1);
        ps0 += __shfl_xor_sync(0xffffffffu, ps0, 2);
        ps1 += __shfl_xor_sync(0xffffffffu, ps1, 1);
        ps1 += __shfl_xor_sync(0xffffffffu, ps1, 2);

        lrow0 += ps0;
        lrow1 += ps1;

        const int srcA = (lane & ~3) | (q >> 1);
        const int srcB = srcA + 2;
        const bool odd = (q & 1);
#pragma unroll
        for (int kt = 0; kt < 4; kt++) {
            float u0 = __shfl_sync(0xffffffffu, s[kt][0], srcA);
            float u1 = __shfl_sync(0xffffffffu, s[kt][1], srcA);
            float u2 = __shfl_sync(0xffffffffu, s[kt][2], srcA);
            float u3 = __shfl_sync(0xffffffffu, s[kt][3], srcA);
            float v0 = __shfl_sync(0xffffffffu, s[kt][0], srcB);
            float v1 = __shfl_sync(0xffffffffu, s[kt][1], srcB);
            float v2 = __shfl_sync(0xffffffffu, s[kt][2], srcB);
            float v3 = __shfl_sync(0xffffffffu, s[kt][3], srcB);
            unsigned pa[4];
            pa[0] = f2tf(odd ? u1 : u0);
            pa[1] = f2tf(odd ? u3 : u2);
            pa[2] = f2tf(odd ? v1 : v0);
            pa[3] = f2tf(odd ? v3 : v2);
#pragma unroll
            for (int dt = 0; dt < 8; dt++) {
                unsigned b0 = __float_as_uint(VS(buf, kt * 8 + q,     dt * 8 + g));
                unsigned b1 = __float_as_uint(VS(buf, kt * 8 + q + 4, dt * 8 + g));
                mma_tf32(o[dt], pa, b0, b1);
            }
        }

        __syncthreads();
        if (t + 2 < NT) {
            stage_kv(sm, buf, Kg, Vg, (t + 2) * KT, tid);
        }
    }

    // epilogue: O/l -> g_AO [B,N,H,Dh], pre-rounded to tf32 for the proj GEMM
    const float il0 = 1.0f / lrow0;
    const float il1 = 1.0f / lrow1;
    const int b = bh >> 4, h = bh & 15;
    const int n0g = blockIdx.x * 128 + w * 16 + g;
    const size_t base0 = (((size_t)b * SEQ + n0g)     * NHEADS + h) * HDIM;
    const size_t base1 = (((size_t)b * SEQ + n0g + 8) * NHEADS + h) * HDIM;
#pragma unroll
    for (int dt = 0; dt < 8; dt++) {
        g_AO[base0 + dt * 8 + 2 * q]     = __uint_as_float(f2tf(o[dt][0] * il0));
        g_AO[base0 + dt * 8 + 2 * q + 1] = __uint_as_float(f2tf(o[dt][1] * il0));
        g_AO[base1 + dt * 8 + 2 * q]     = __uint_as_float(f2tf(o[dt][2] * il1));
        g_AO[base1 + dt * 8 + 2 * q + 1] = __uint_as_float(f2tf(o[dt][3] * il1));
    }
}

// vectorized bias add (row length 1024 floats = 256 float4)
__global__ void bias_add_kernel(float4* __restrict__ out,
                                const float* __restrict__ bias, int total4)
{
    int i = blockIdx.x * blockDim.x + threadIdx.x;
    if (i < total4) {
        int c = (i << 2) & (DIMC - 1);
        float4 v = out[i];
        v.x += __ldg(bias + c);
        v.y += __ldg(bias + c + 1);
        v.z += __ldg(bias + c + 2);
        v.w += __ldg(bias + c + 3);
        out[i] = v;
    }
}

extern "C" void kernel_launch(void* const* d_in, const int* in_sizes, int n_in,
                              void* d_out, int out_size)
{
    (void)in_sizes; (void)n_in; (void)out_size;
    const float* x     = (const float*)d_in[0];   // [4,2048,1024]
    const float* wqkv  = (const float*)d_in[1];   // [3072,1024]
    const float* wproj = (const float*)d_in[2];   // [1024,1024]
    const float* bproj = (const float*)d_in[3];   // [1024]
    float* out = (float*)d_out;                   // [4,2048,1024]

    cudaFuncSetAttribute(attn_kernel,
                         cudaFuncAttributeMaxDynamicSharedMemorySize,
                         ATT_SMEM_BYTES);

    float *xt, *wqt, *wpt;
    cudaGetSymbolAddress((void**)&xt,  g_Xt);
    cudaGetSymbolAddress((void**)&wqt, g_Wqt);
    cudaGetSymbolAddress((void**)&wpt, g_Wpt);

    // 1) pre-round GEMM inputs to tf32 bits
    round_tf32_kernel<<<(MTOT * DIMC / 4 + 255) / 256, 256>>>(
        (const float4*)x, (float4*)xt, MTOT * DIMC / 4);
    round_tf32_kernel<<<(3 * DIMC * DIMC / 4 + 255) / 256, 256>>>(
        (const float4*)wqkv, (float4*)wqt, 3 * DIMC * DIMC / 4);
    round_tf32_kernel<<<(DIMC * DIMC / 4 + 255) / 256, 256>>>(
        (const float4*)wproj, (float4*)wpt, DIMC * DIMC / 4);

    // 2) QKV GEMM -> g_Q/g_K/g_V
    gemm_tf32_kernel<0><<<dim3(3 * DIMC / 128, MTOT / 128), 256>>>(
        xt, wqt, nullptr, MTOT, 3 * DIMC, DIMC);

    // 3) attention -> g_AO
    attn_kernel<<<dim3(SEQ / 128, BATCH * NHEADS), 256, ATT_SMEM_BYTES>>>();

    // 4) projection GEMM -> out
    gemm_tf32_kernel<1><<<dim3(DIMC / 128, MTOT / 128), 256>>>(
        nullptr, wpt, out, MTOT, DIMC, DIMC);

    // 5) bias
    bias_add_kernel<<<(MTOT * DIMC / 4 + 255) / 256, 256>>>(
        (float4*)out, bproj, MTOT * DIMC / 4);
}

// round 15
// speedup vs baseline: 1.8267x; 1.0129x over previous
#include <cstdint>
#include <stdint.h>
#include <cuda_runtime.h>
#include <cuda_bf16.h>

#define DIMC    1024
#define NHEADS  16
#define HDIM    64
#define BATCH   4
#define SEQ     2048
#define MTOT    (BATCH*SEQ)      // 8192
// scale folded with log2(e): softmax runs in base-2 domain
#define ATT_SCALE_LOG2E 0.18033688011112042f   // (1/8) * log2(e)

// ---------------- scratch (static device globals; no allocation) ----------------
__device__ float g_Q[(size_t)BATCH*NHEADS*SEQ*HDIM];   // [B,H,N,Dh]
__device__ float g_K[(size_t)BATCH*NHEADS*SEQ*HDIM];
__device__ float g_V[(size_t)BATCH*NHEADS*SEQ*HDIM];
__device__ float g_AO[(size_t)MTOT*DIMC];              // [B,N,H,Dh] == [M, C]
// tf32-pre-rounded GEMM operands (fp32 containers holding tf32 bit patterns)
__device__ float g_Xt [(size_t)MTOT*DIMC];
__device__ float g_Wqt[(size_t)3*DIMC*DIMC];
__device__ float g_Wpt[(size_t)DIMC*DIMC];

// round-to-nearest fp32 -> tf32 (RNA is load-bearing)
__device__ __forceinline__ unsigned f2tf(float f) {
    unsigned u;
    asm("cvt.rna.tf32.f32 %0, %1;" : "=r"(u) : "f"(f));
    return u;
}

__device__ __forceinline__ void mma_tf32(float c[4], const unsigned a[4],
                                         unsigned b0, unsigned b1) {
    asm volatile(
        "mma.sync.aligned.m16n8k8.row.col.f32.tf32.tf32.f32 "
        "{%0,%1,%2,%3},{%4,%5,%6,%7},{%8,%9},{%0,%1,%2,%3};"
        : "+f"(c[0]), "+f"(c[1]), "+f"(c[2]), "+f"(c[3])
        : "r"(a[0]), "r"(a[1]), "r"(a[2]), "r"(a[3]), "r"(b0), "r"(b1));
}

// fast exp2 on the FMA pipe (x <= 0, clamped at -80); fexp2(0) == 1.0f exactly
__device__ __forceinline__ float fexp2(float x) {
    x = fmaxf(x, -80.0f);
    float t = x + 12582912.0f;
    int   i = __float_as_int(t);
    float r = t - 12582912.0f;
    float y = (x - r) * 0.6931471805599453f;
    float p = fmaf(y, 0.04166666667f, 0.16666666667f);
    p = fmaf(y, p, 0.5f);
    p = fmaf(y, p, 1.0f);
    p = fmaf(y, p, 1.0f);
    return __int_as_float(__float_as_int(p) + (i << 23));
}

// ---------------- cp.async helpers ----------------
__device__ __forceinline__ void cp16(void* smem, const void* gmem) {
    unsigned s = (unsigned)__cvta_generic_to_shared(smem);
    asm volatile("cp.async.ca.shared.global [%0], [%1], 16;\n" :: "r"(s), "l"(gmem));
}
#define CP_COMMIT()  asm volatile("cp.async.commit_group;\n" ::: "memory")
#define CP_WAIT0()   asm volatile("cp.async.wait_group 0;\n" ::: "memory")
#define CP_WAIT1()   asm volatile("cp.async.wait_group 1;\n" ::: "memory")

// ================================================================================
// prepass: round fp32 -> tf32 bit pattern (keeps fp32 container)
// ================================================================================
__global__ void round_tf32_kernel(const float4* __restrict__ in,
                                  float4* __restrict__ out, int n4)
{
    int i = blockIdx.x * blockDim.x + threadIdx.x;
    if (i >= n4) return;
    float4 v = in[i];
    v.x = __uint_as_float(f2tf(v.x));
    v.y = __uint_as_float(f2tf(v.y));
    v.z = __uint_as_float(f2tf(v.z));
    v.w = __uint_as_float(f2tf(v.w));
    out[i] = v;
}

// ================================================================================
// Raw-PTX TF32 GEMM: C[M,N] = A[M,K] @ W[N,K]^T.
// 3-stage cp.async pipeline, ONE __syncthreads per BK iteration:
//   iter kt: wait(stage kt arrived); sync; stage kt+2 into (kt+2)%3 (buffer last
//   read in iter kt-1, fenced by this sync); compute buf kt%3.
// Block 128x128, BK=16, 8 warps (2m x 4n), warp tile 64x32 as 4m x 4n m16n8k8.
// EPI==0: scatter to g_Q/g_K/g_V (tf32 pre-round, Q pre-scaled).
// EPI==1: A = g_AO, C -> Out row-major with fused bias.
// Dynamic smem: 3 stages x (A 2560 + B 2560 floats) = 61440 B.
// ================================================================================
#define GS_A(st, r, c) smg[(st) * 5120 + (r) * 20 + (c)]
#define GS_B(st, r, c) smg[(st) * 5120 + 2560 + (r) * 20 + (c)]
#define GEMM_SMEM_BYTES (3 * 5120 * 4)   // 61440

template<int EPI>
__global__ __launch_bounds__(256, 2)
void gemm_tf32_kernel(const float* __restrict__ A_in,
                      const float* __restrict__ W,
                      const float* __restrict__ bias,
                      float* __restrict__ Out,
                      int M, int N, int K)
{
    extern __shared__ float smg[];
    constexpr int BM = 128, BK = 16;

    const float* A = (EPI == 1) ? (const float*)g_AO : A_in;

    const int tid  = threadIdx.x;
    const int wid  = tid >> 5;
    const int lane = tid & 31;
    const int g    = lane >> 2;
    const int q    = lane & 3;
    const int wm   = wid & 1;
    const int wn   = wid >> 1;
    const int m0   = blockIdx.y * BM;
    const int cn   = blockIdx.x * 128;

    const int r0 = tid >> 2,         q0 = tid & 3;
    const int r1 = (tid + 256) >> 2, q1 = (tid + 256) & 3;

    float acc[4][4][4];
#pragma unroll
    for (int mt = 0; mt < 4; mt++)
#pragma unroll
        for (int nt = 0; nt < 4; nt++)
            acc[mt][nt][0] = acc[mt][nt][1] = acc[mt][nt][2] = acc[mt][nt][3] = 0.0f;

    const int nk = K / BK;

    // stage helper (lambda-free for reg economy)
#define GEMM_STAGE(st, kb)                                                        \
    do {                                                                          \
        cp16(&GS_A(st, r0, q0 * 4), A + (size_t)(m0 + r0) * K + (kb) + q0 * 4);   \
        cp16(&GS_A(st, r1, q1 * 4), A + (size_t)(m0 + r1) * K + (kb) + q1 * 4);   \
        cp16(&GS_B(st, r0, q0 * 4), W + (size_t)(cn + r0) * K + (kb) + q0 * 4);   \
        cp16(&GS_B(st, r1, q1 * 4), W + (size_t)(cn + r1) * K + (kb) + q1 * 4);   \
        CP_COMMIT();                                                              \
    } while (0)

    GEMM_STAGE(0, 0);
    GEMM_STAGE(1, BK);

    int buf = 0;
    for (int kt = 0; kt < nk; kt++) {
        if (kt + 1 < nk) { CP_WAIT1(); } else { CP_WAIT0(); }
        __syncthreads();

        if (kt + 2 < nk) {
            int st = (kt + 2) % 3;
            GEMM_STAGE(st, (kt + 2) * BK);
        }

        // load all fragments for BK=16 (2 k8-steps); conflict-free (pitch 20)
        unsigned a[2][4][4];
        unsigned b[2][4][2];
#pragma unroll
        for (int ks = 0; ks < 2; ks++) {
#pragma unroll
            for (int mt = 0; mt < 4; mt++) {
                const int row = wm * 64 + mt * 16;
                a[ks][mt][0] = __float_as_uint(GS_A(buf, row + g,     ks * 8 + q));
                a[ks][mt][1] = __float_as_uint(GS_A(buf, row + g + 8, ks * 8 + q));
                a[ks][mt][2] = __float_as_uint(GS_A(buf, row + g,     ks * 8 + q + 4));
                a[ks][mt][3] = __float_as_uint(GS_A(buf, row + g + 8, ks * 8 + q + 4));
            }
#pragma unroll
            for (int nt = 0; nt < 4; nt++) {
                const int col = wn * 32 + nt * 8;
                b[ks][nt][0] = __float_as_uint(GS_B(buf, col + g, ks * 8 + q));
                b[ks][nt][1] = __float_as_uint(GS_B(buf, col + g, ks * 8 + q + 4));
            }
        }
#pragma unroll
        for (int ks = 0; ks < 2; ks++)
#pragma unroll
            for (int mt = 0; mt < 4; mt++)
#pragma unroll
                for (int nt = 0; nt < 4; nt++)
                    mma_tf32(acc[mt][nt], a[ks][mt], b[ks][nt][0], b[ks][nt][1]);

        buf = (buf + 1) % 3;
    }

    // epilogue: per m16n8 acc: c0,c1 = (row g, col 2q,2q+1); c2,c3 = (row g+8, ...)
#pragma unroll
    for (int mt = 0; mt < 4; mt++) {
        const int row0 = m0 + wm * 64 + mt * 16 + g;
#pragma unroll
        for (int nt = 0; nt < 4; nt++) {
            const int j = cn + wn * 32 + nt * 8 + 2 * q;
            if (EPI == 0) {
                const int t = j >> 10, r = j & 1023, h = r >> 6, d = r & 63;
                const int bI = row0 >> 11, n0 = row0 & 2047;
                float* base = (t == 0) ? g_Q : ((t == 1) ? g_K : g_V);
                const float mult = (t == 0) ? ATT_SCALE_LOG2E : 1.0f;
                float* p0 = base + (((size_t)(bI * NHEADS + h) * SEQ + n0) * HDIM + d);
                float2 v0, v1;
                v0.x = __uint_as_float(f2tf(acc[mt][nt][0] * mult));
                v0.y = __uint_as_float(f2tf(acc[mt][nt][1] * mult));
                v1.x = __uint_as_float(f2tf(acc[mt][nt][2] * mult));
                v1.y = __uint_as_float(f2tf(acc[mt][nt][3] * mult));
                *reinterpret_cast<float2*>(p0) = v0;
                *reinterpret_cast<float2*>(p0 + 8 * HDIM) = v1;   // row0+8
            } else {
                const float b0 = __ldg(bias + j);
                const float b1 = __ldg(bias + j + 1);
                float2 v0 = { acc[mt][nt][0] + b0, acc[mt][nt][1] + b1 };
                float2 v1 = { acc[mt][nt][2] + b0, acc[mt][nt][3] + b1 };
                *reinterpret_cast<float2*>(Out + (size_t)row0 * N + j) = v0;
                *reinterpret_cast<float2*>(Out + (size_t)(row0 + 8) * N + j) = v1;
            }
        }
    }
#undef GEMM_STAGE
}

// ================================================================================
// Flash attention (unchanged, passing): grid (N/128, B*H), 256 thr, 2 CTAs/SM,
// KT=32, cp.async double-buffered, shuffle P-repack, rescale skip.
// ================================================================================
#define KT 32
#define KS(b,r,c) sm[(((b)*KT + (r)) * 68) + (c)]
#define VS(b,r,c) sm[VOFF + (((b)*KT + (r)) * 72) + (c)]
#define VOFF (2*KT*68)
#define ATT_SMEM_BYTES ((2*KT*68 + 2*KT*72) * 4)   // 35840 B

__device__ __forceinline__ void stage_kv(float* sm, int buf,
                                         const float* Kg, const float* Vg,
                                         int j, int tid)
{
#pragma unroll
    for (int it = 0; it < 2; it++) {
        int lin = tid + it * 256;
        int row = lin >> 4, ch = lin & 15;
        cp16(&KS(buf, row, ch * 4), Kg + (size_t)(j + row) * HDIM + ch * 4);
        cp16(&VS(buf, row, ch * 4), Vg + (size_t)(j + row) * HDIM + ch * 4);
    }
    CP_COMMIT();
}

__global__ __launch_bounds__(256, 2)
void attn_kernel()
{
    extern __shared__ float sm[];

    const int tid  = threadIdx.x;
    const int w    = tid >> 5;
    const int lane = tid & 31;
    const int g    = lane >> 2;
    const int q    = lane & 3;

    const int bh = blockIdx.y;
    const float* Qg = g_Q + (size_t)bh * SEQ * HDIM;
    const float* Kg = g_K + (size_t)bh * SEQ * HDIM;
    const float* Vg = g_V + (size_t)bh * SEQ * HDIM;

    const int q0 = blockIdx.x * 128 + w * 16;

    unsigned qa[8][4];
#pragma unroll
    for (int kt = 0; kt < 8; kt++) {
        int c0 = kt * 8 + q;
        qa[kt][0] = __float_as_uint(Qg[(size_t)(q0 + g)     * HDIM + c0]);
        qa[kt][1] = __float_as_uint(Qg[(size_t)(q0 + g + 8) * HDIM + c0]);
        qa[kt][2] = __float_as_uint(Qg[(size_t)(q0 + g)     * HDIM + c0 + 4]);
        qa[kt][3] = __float_as_uint(Qg[(size_t)(q0 + g + 8) * HDIM + c0 + 4]);
    }

    float o[8][4];
#pragma unroll
    for (int dt = 0; dt < 8; dt++)
        o[dt][0] = o[dt][1] = o[dt][2] = o[dt][3] = 0.0f;
    float mrow0 = -INFINITY, mrow1 = -INFINITY;
    float lrow0 = 0.0f, lrow1 = 0.0f;

    stage_kv(sm, 0, Kg, Vg, 0,  tid);
    stage_kv(sm, 1, Kg, Vg, KT, tid);

    constexpr int NT = SEQ / KT;
    for (int t = 0; t < NT; t++) {
        const int buf = t & 1;
        if (t + 1 < NT) { CP_WAIT1(); } else { CP_WAIT0(); }
        __syncthreads();

        float s[4][4];
#pragma unroll
        for (int nt = 0; nt < 4; nt++)
            s[nt][0] = s[nt][1] = s[nt][2] = s[nt][3] = 0.0f;
#pragma unroll
        for (int kt = 0; kt < 8; kt++) {
#pragma unroll
            for (int nt = 0; nt < 4; nt++) {
                unsigned b0 = __float_as_uint(KS(buf, nt * 8 + g, kt * 8 + q));
                unsigned b1 = __float_as_uint(KS(buf, nt * 8 + g, kt * 8 + q + 4));
                mma_tf32(s[nt], qa[kt], b0, b1);
            }
        }

        float rm0 = -INFINITY, rm1 = -INFINITY;
#pragma unroll
        for (int nt = 0; nt < 4; nt++) {
            rm0 = fmaxf(rm0, fmaxf(s[nt][0], s[nt][1]));
            rm1 = fmaxf(rm1, fmaxf(s[nt][2], s[nt][3]));
        }
        rm0 = fmaxf(rm0, __shfl_xor_sync(0xffffffffu, rm0, 1));
        rm0 = fmaxf(rm0, __shfl_xor_sync(0xffffffffu, rm0, 2));
        rm1 = fmaxf(rm1, __shfl_xor_sync(0xffffffffu, rm1, 1));
        rm1 = fmaxf(rm1, __shfl_xor_sync(0xffffffffu, rm1, 2));

        float mn0 = fmaxf(mrow0, rm0);
        float mn1 = fmaxf(mrow1, rm1);

        bool chg = (mn0 > mrow0) || (mn1 > mrow1);
        if (__ballot_sync(0xffffffffu, chg)) {
            float al0 = fexp2(mrow0 - mn0);
            float al1 = fexp2(mrow1 - mn1);
            lrow0 *= al0;
            lrow1 *= al1;
#pragma unroll
            for (int dt = 0; dt < 8; dt++) {
                o[dt][0] *= al0; o[dt][1] *= al0;
                o[dt][2] *= al1; o[dt][3] *= al1;
            }
            mrow0 = mn0;
            mrow1 = mn1;
        }

        float ps0 = 0.0f, ps1 = 0.0f;
#pragma unroll
        for (int nt = 0; nt < 4; nt++) {
            s[nt][0] = fexp2(s[nt][0] - mrow0);
            s[nt][1] = fexp2(s[nt][1] - mrow0);
            s[nt][2] = fexp2(s[nt][2] - mrow1);
            s[nt][3] = fexp2(s[nt][3] - mrow1);
            ps0 += s[nt][0] + s[nt][1];
            ps1 += s[nt][2] + s[nt][3];
        }
        ps0 += __shfl_xor_sync(0xffffffffu, ps0, 1);
        ps0 += __shfl_xor_sync(0xffffffffu, ps0, 2);
        ps1 += __shfl_xor_sync(0xffffffffu, ps1, 1);
        ps1 += __shfl_xor_sync(0xffffffffu, ps1, 2);

        lrow0 += ps0;
        lrow1 += ps1;

        const int srcA = (lane & ~3) | (q >> 1);
        const int srcB = srcA + 2;
        const bool odd = (q & 1);
#pragma unroll
        for (int kt = 0; kt < 4; kt++) {
            float u0 = __shfl_sync(0xffffffffu, s[kt][0], srcA);
            float u1 = __shfl_sync(0xffffffffu, s[kt][1], srcA);
            float u2 = __shfl_sync(0xffffffffu, s[kt][2], srcA);
            float u3 = __shfl_sync(0xffffffffu, s[kt][3], srcA);
            float v0 = __shfl_sync(0xffffffffu, s[kt][0], srcB);
            float v1 = __shfl_sync(0xffffffffu, s[kt][1], srcB);
            float v2 = __shfl_sync(0xffffffffu, s[kt][2], srcB);
            float v3 = __shfl_sync(0xffffffffu, s[kt][3], srcB);
            unsigned pa[4];
            pa[0] = f2tf(odd ? u1 : u0);
            pa[1] = f2tf(odd ? u3 : u2);
            pa[2] = f2tf(odd ? v1 : v0);
            pa[3] = f2tf(odd ? v3 : v2);
#pragma unroll
            for (int dt = 0; dt < 8; dt++) {
                unsigned b0 = __float_as_uint(VS(buf, kt * 8 + q,     dt * 8 + g));
                unsigned b1 = __float_as_uint(VS(buf, kt * 8 + q + 4, dt * 8 + g));
                mma_tf32(o[dt], pa, b0, b1);
            }
        }

        __syncthreads();
        if (t + 2 < NT) {
            stage_kv(sm, buf, Kg, Vg, (t + 2) * KT, tid);
        }
    }

    // epilogue: O/l -> g_AO [B,N,H,Dh], pre-rounded to tf32 for the proj GEMM
    const float il0 = 1.0f / lrow0;
    const float il1 = 1.0f / lrow1;
    const int b = bh >> 4, h = bh & 15;
    const int n0g = blockIdx.x * 128 + w * 16 + g;
    const size_t base0 = (((size_t)b * SEQ + n0g)     * NHEADS + h) * HDIM;
    const size_t base1 = (((size_t)b * SEQ + n0g + 8) * NHEADS + h) * HDIM;
#pragma unroll
    for (int dt = 0; dt < 8; dt++) {
        g_AO[base0 + dt * 8 + 2 * q]     = __uint_as_float(f2tf(o[dt][0] * il0));
        g_AO[base0 + dt * 8 + 2 * q + 1] = __uint_as_float(f2tf(o[dt][1] * il0));
        g_AO[base1 + dt * 8 + 2 * q]     = __uint_as_float(f2tf(o[dt][2] * il1));
        g_AO[base1 + dt * 8 + 2 * q + 1] = __uint_as_float(f2tf(o[dt][3] * il1));
    }
}

extern "C" void kernel_launch(void* const* d_in, const int* in_sizes, int n_in,
                              void* d_out, int out_size)
{
    (void)in_sizes; (void)n_in; (void)out_size;
    const float* x     = (const float*)d_in[0];   // [4,2048,1024]
    const float* wqkv  = (const float*)d_in[1];   // [3072,1024]
    const float* wproj = (const float*)d_in[2];   // [1024,1024]
    const float* bproj = (const float*)d_in[3];   // [1024]
    float* out = (float*)d_out;                   // [4,2048,1024]

    cudaFuncSetAttribute(attn_kernel,
                         cudaFuncAttributeMaxDynamicSharedMemorySize,
                         ATT_SMEM_BYTES);
    cudaFuncSetAttribute(gemm_tf32_kernel<0>,
                         cudaFuncAttributeMaxDynamicSharedMemorySize,
                         GEMM_SMEM_BYTES);
    cudaFuncSetAttribute(gemm_tf32_kernel<1>,
                         cudaFuncAttributeMaxDynamicSharedMemorySize,
                         GEMM_SMEM_BYTES);

    float *xt, *wqt, *wpt;
    cudaGetSymbolAddress((void**)&xt,  g_Xt);
    cudaGetSymbolAddress((void**)&wqt, g_Wqt);
    cudaGetSymbolAddress((void**)&wpt, g_Wpt);

    // 1) pre-round GEMM inputs to tf32 bits
    round_tf32_kernel<<<(MTOT * DIMC / 4 + 255) / 256, 256>>>(
        (const float4*)x, (float4*)xt, MTOT * DIMC / 4);
    round_tf32_kernel<<<(3 * DIMC * DIMC / 4 + 255) / 256, 256>>>(
        (const float4*)wqkv, (float4*)wqt, 3 * DIMC * DIMC / 4);
    round_tf32_kernel<<<(DIMC * DIMC / 4 + 255) / 256, 256>>>(
        (const float4*)wproj, (float4*)wpt, DIMC * DIMC / 4);

    // 2) QKV GEMM -> g_Q/g_K/g_V
    gemm_tf32_kernel<0><<<dim3(3 * DIMC / 128, MTOT / 128), 256, GEMM_SMEM_BYTES>>>(
        xt, wqt, nullptr, nullptr, MTOT, 3 * DIMC, DIMC);

    // 3) attention -> g_AO
    attn_kernel<<<dim3(SEQ / 128, BATCH * NHEADS), 256, ATT_SMEM_BYTES>>>();

    // 4) projection GEMM (+fused bias) -> out
    gemm_tf32_kernel<1><<<dim3(DIMC / 128, MTOT / 128), 256, GEMM_SMEM_BYTES>>>(
        nullptr, wpt, bproj, out, MTOT, DIMC, DIMC);
}

// round 17
// speedup vs baseline: 1.9625x; 1.0743x over previous
#include <cstdint>
#include <stdint.h>
#include <cuda_runtime.h>
#include <cuda_bf16.h>

#define DIMC    1024
#define NHEADS  16
#define HDIM    64
#define BATCH   4
#define SEQ     2048
#define MTOT    (BATCH*SEQ)      // 8192
// scale folded with log2(e): softmax runs in base-2 domain
#define ATT_SCALE_LOG2E 0.18033688011112042f   // (1/8) * log2(e)

// ---------------- scratch (static device globals; no allocation) ----------------
__device__ float g_Q[(size_t)BATCH*NHEADS*SEQ*HDIM];   // [B,H,N,Dh]
__device__ float g_K[(size_t)BATCH*NHEADS*SEQ*HDIM];
__device__ float g_V[(size_t)BATCH*NHEADS*SEQ*HDIM];
__device__ float g_AO[(size_t)MTOT*DIMC];              // [B,N,H,Dh] == [M, C]
// tf32-pre-rounded GEMM operands (fp32 containers holding tf32 bit patterns)
__device__ float g_Xt [(size_t)MTOT*DIMC];
__device__ float g_Wqt[(size_t)3*DIMC*DIMC];
__device__ float g_Wpt[(size_t)DIMC*DIMC];

// round-to-nearest fp32 -> tf32 (RNA is load-bearing)
__device__ __forceinline__ unsigned f2tf(float f) {
    unsigned u;
    asm("cvt.rna.tf32.f32 %0, %1;" : "=r"(u) : "f"(f));
    return u;
}

__device__ __forceinline__ void mma_tf32(float c[4], const unsigned a[4],
                                         unsigned b0, unsigned b1) {
    asm volatile(
        "mma.sync.aligned.m16n8k8.row.col.f32.tf32.tf32.f32 "
        "{%0,%1,%2,%3},{%4,%5,%6,%7},{%8,%9},{%0,%1,%2,%3};"
        : "+f"(c[0]), "+f"(c[1]), "+f"(c[2]), "+f"(c[3])
        : "r"(a[0]), "r"(a[1]), "r"(a[2]), "r"(a[3]), "r"(b0), "r"(b1));
}

// ldmatrix x4 (b16 view): with the right per-lane addresses this yields exact
// tf32 m16n8k8 fragments (b32 col q == b16 col pair 2q,2q+1).
__device__ __forceinline__ void ldsm_x4(unsigned r[4], uint32_t addr) {
    asm volatile(
        "ldmatrix.sync.aligned.m8n8.x4.shared.b16 {%0,%1,%2,%3}, [%4];"
        : "=r"(r[0]), "=r"(r[1]), "=r"(r[2]), "=r"(r[3]) : "r"(addr));
}

// fast exp2 on the FMA pipe (x <= 0, clamped at -80); fexp2(0) == 1.0f exactly
__device__ __forceinline__ float fexp2(float x) {
    x = fmaxf(x, -80.0f);
    float t = x + 12582912.0f;
    int   i = __float_as_int(t);
    float r = t - 12582912.0f;
    float y = (x - r) * 0.6931471805599453f;
    float p = fmaf(y, 0.04166666667f, 0.16666666667f);
    p = fmaf(y, p, 0.5f);
    p = fmaf(y, p, 1.0f);
    p = fmaf(y, p, 1.0f);
    return __int_as_float(__float_as_int(p) + (i << 23));
}

// ---------------- cp.async helpers ----------------
__device__ __forceinline__ void cp16(void* smem, const void* gmem) {
    unsigned s = (unsigned)__cvta_generic_to_shared(smem);
    asm volatile("cp.async.ca.shared.global [%0], [%1], 16;\n" :: "r"(s), "l"(gmem));
}
#define CP_COMMIT()  asm volatile("cp.async.commit_group;\n" ::: "memory")
#define CP_WAIT0()   asm volatile("cp.async.wait_group 0;\n" ::: "memory")
#define CP_WAIT1()   asm volatile("cp.async.wait_group 1;\n" ::: "memory")

// ================================================================================
// prepass: round fp32 -> tf32 bit pattern (keeps fp32 container)
// ================================================================================
__global__ void round_tf32_kernel(const float4* __restrict__ in,
                                  float4* __restrict__ out, int n4)
{
    int i = blockIdx.x * blockDim.x + threadIdx.x;
    if (i >= n4) return;
    float4 v = in[i];
    v.x = __uint_as_float(f2tf(v.x));
    v.y = __uint_as_float(f2tf(v.y));
    v.z = __uint_as_float(f2tf(v.z));
    v.w = __uint_as_float(f2tf(v.w));
    out[i] = v;
}

// ================================================================================
// Raw-PTX TF32 GEMM with LDSM fragment loads.
// 3-stage cp.async, one sync/iter. Block 128x128, BK=16, 8 warps (2m x 4n),
// warp tile 64x32. Fragments via ldmatrix.x4: 12 LDSM/iter replace 48 LDS/iter.
// Pitch 20 floats: rows start at banks {0,20,8,28,16,4,24,12} -> 8 rows tile all
// 32 banks disjointly (conflict-free ldmatrix), 16B segments aligned (80=5*16).
// EPI==0: scatter to g_Q/g_K/g_V (tf32 pre-round, Q pre-scaled).
// EPI==1: A = g_AO, C -> Out row-major with fused bias.
// ================================================================================
#define GS_A(st, r, c) smg[(st) * 5120 + (r) * 20 + (c)]
#define GS_B(st, r, c) smg[(st) * 5120 + 2560 + (r) * 20 + (c)]
#define STAGE_BYTES 20480
#define GEMM_SMEM_BYTES (3 * STAGE_BYTES)   // 61440

template<int EPI>
__global__ __launch_bounds__(256, 2)
void gemm_tf32_kernel(const float* __restrict__ A_in,
                      const float* __restrict__ W,
                      const float* __restrict__ bias,
                      float* __restrict__ Out,
                      int M, int N, int K)
{
    extern __shared__ float smg[];
    constexpr int BM = 128, BK = 16;

    const float* A = (EPI == 1) ? (const float*)g_AO : A_in;

    const int tid  = threadIdx.x;
    const int wid  = tid >> 5;
    const int lane = tid & 31;
    const int g    = lane >> 2;
    const int q    = lane & 3;
    const int wm   = wid & 1;
    const int wn   = wid >> 1;
    const int m0   = blockIdx.y * BM;
    const int cn   = blockIdx.x * 128;

    const int r0 = tid >> 2,         q0 = tid & 3;
    const int r1 = (tid + 256) >> 2, q1 = (tid + 256) & 3;

    // ---- per-lane LDSM addresses (byte offsets within a stage) ----
    // A fragment (ks, mt): matrices 0..3 from lane groups 0-7/8-15/16-23/24-31:
    //   rows rb+(sub&1)*8+rr at col ks*8+(sub>>1)*4  -> r0..r3 = tf32 A frag
    // B pair (ks, pr): rows (nt)*8+rr at col ks*8+(sub&1)*4, nt = pr*2+(sub>>1)
    const uint32_t smbase = (uint32_t)__cvta_generic_to_shared(smg);
    const int sub = lane >> 3, rr = lane & 7;
    uint32_t aoff[2][4], boff[2][2];
#pragma unroll
    for (int ks = 0; ks < 2; ks++) {
#pragma unroll
        for (int mt = 0; mt < 4; mt++) {
            int row = wm * 64 + mt * 16 + (sub & 1) * 8 + rr;
            int col = ks * 8 + (sub >> 1) * 4;
            aoff[ks][mt] = (uint32_t)((row * 20 + col) * 4);
        }
#pragma unroll
        for (int pr = 0; pr < 2; pr++) {
            int row = wn * 32 + (pr * 2 + (sub >> 1)) * 8 + rr;
            int col = ks * 8 + (sub & 1) * 4;
            boff[ks][pr] = (uint32_t)((2560 + row * 20 + col) * 4);
        }
    }

    float acc[4][4][4];
#pragma unroll
    for (int mt = 0; mt < 4; mt++)
#pragma unroll
        for (int nt = 0; nt < 4; nt++)
            acc[mt][nt][0] = acc[mt][nt][1] = acc[mt][nt][2] = acc[mt][nt][3] = 0.0f;

    const int nk = K / BK;

#define GEMM_STAGE(st, kb)                                                        \
    do {                                                                          \
        cp16(&GS_A(st, r0, q0 * 4), A + (size_t)(m0 + r0) * K + (kb) + q0 * 4);   \
        cp16(&GS_A(st, r1, q1 * 4), A + (size_t)(m0 + r1) * K + (kb) + q1 * 4);   \
        cp16(&GS_B(st, r0, q0 * 4), W + (size_t)(cn + r0) * K + (kb) + q0 * 4);   \
        cp16(&GS_B(st, r1, q1 * 4), W + (size_t)(cn + r1) * K + (kb) + q1 * 4);   \
        CP_COMMIT();                                                              \
    } while (0)

    GEMM_STAGE(0, 0);
    GEMM_STAGE(1, BK);

    int buf = 0;
    for (int kt = 0; kt < nk; kt++) {
        if (kt + 1 < nk) { CP_WAIT1(); } else { CP_WAIT0(); }
        __syncthreads();

        if (kt + 2 < nk) {
            int st = (kt + 2) % 3;
            GEMM_STAGE(st, (kt + 2) * BK);
        }

        const uint32_t sbase = smbase + (uint32_t)buf * STAGE_BYTES;

        unsigned a[2][4][4];
        unsigned b[2][4][2];
#pragma unroll
        for (int ks = 0; ks < 2; ks++) {
#pragma unroll
            for (int mt = 0; mt < 4; mt++)
                ldsm_x4(a[ks][mt], sbase + aoff[ks][mt]);
#pragma unroll
            for (int pr = 0; pr < 2; pr++) {
                unsigned tmp[4];
                ldsm_x4(tmp, sbase + boff[ks][pr]);
                b[ks][pr * 2    ][0] = tmp[0];
                b[ks][pr * 2    ][1] = tmp[1];
                b[ks][pr * 2 + 1][0] = tmp[2];
                b[ks][pr * 2 + 1][1] = tmp[3];
            }
        }
#pragma unroll
        for (int ks = 0; ks < 2; ks++)
#pragma unroll
            for (int mt = 0; mt < 4; mt++)
#pragma unroll
                for (int nt = 0; nt < 4; nt++)
                    mma_tf32(acc[mt][nt], a[ks][mt], b[ks][nt][0], b[ks][nt][1]);

        buf = (buf + 1) % 3;
    }

    // epilogue: per m16n8 acc: c0,c1 = (row g, col 2q,2q+1); c2,c3 = (row g+8, ...)
#pragma unroll
    for (int mt = 0; mt < 4; mt++) {
        const int row0 = m0 + wm * 64 + mt * 16 + g;
#pragma unroll
        for (int nt = 0; nt < 4; nt++) {
            const int j = cn + wn * 32 + nt * 8 + 2 * q;
            if (EPI == 0) {
                const int t = j >> 10, r = j & 1023, h = r >> 6, d = r & 63;
                const int bI = row0 >> 11, n0 = row0 & 2047;
                float* base = (t == 0) ? g_Q : ((t == 1) ? g_K : g_V);
                const float mult = (t == 0) ? ATT_SCALE_LOG2E : 1.0f;
                float* p0 = base + (((size_t)(bI * NHEADS + h) * SEQ + n0) * HDIM + d);
                float2 v0, v1;
                v0.x = __uint_as_float(f2tf(acc[mt][nt][0] * mult));
                v0.y = __uint_as_float(f2tf(acc[mt][nt][1] * mult));
                v1.x = __uint_as_float(f2tf(acc[mt][nt][2] * mult));
                v1.y = __uint_as_float(f2tf(acc[mt][nt][3] * mult));
                *reinterpret_cast<float2*>(p0) = v0;
                *reinterpret_cast<float2*>(p0 + 8 * HDIM) = v1;   // row0+8
            } else {
                const float b0 = __ldg(bias + j);
                const float b1 = __ldg(bias + j + 1);
                float2 v0 = { acc[mt][nt][0] + b0, acc[mt][nt][1] + b1 };
                float2 v1 = { acc[mt][nt][2] + b0, acc[mt][nt][3] + b1 };
                *reinterpret_cast<float2*>(Out + (size_t)row0 * N + j) = v0;
                *reinterpret_cast<float2*>(Out + (size_t)(row0 + 8) * N + j) = v1;
            }
        }
    }
#undef GEMM_STAGE
}

// ================================================================================
// Flash attention (unchanged, passing): grid (N/128, B*H), 256 thr, 2 CTAs/SM,
// KT=32, cp.async double-buffered, shuffle P-repack, rescale skip.
// ================================================================================
#define KT 32
#define KS(b,r,c) sm[(((b)*KT + (r)) * 68) + (c)]
#define VS(b,r,c) sm[VOFF + (((b)*KT + (r)) * 72) + (c)]
#define VOFF (2*KT*68)
#define ATT_SMEM_BYTES ((2*KT*68 + 2*KT*72) * 4)   // 35840 B

__device__ __forceinline__ void stage_kv(float* sm, int buf,
                                         const float* Kg, const float* Vg,
                                         int j, int tid)
{
#pragma unroll
    for (int it = 0; it < 2; it++) {
        int lin = tid + it * 256;
        int row = lin >> 4, ch = lin & 15;
        cp16(&KS(buf, row, ch * 4), Kg + (size_t)(j + row) * HDIM + ch * 4);
        cp16(&VS(buf, row, ch * 4), Vg + (size_t)(j + row) * HDIM + ch * 4);
    }
    CP_COMMIT();
}

__global__ __launch_bounds__(256, 2)
void attn_kernel()
{
    extern __shared__ float sm[];

    const int tid  = threadIdx.x;
    const int w    = tid >> 5;
    const int lane = tid & 31;
    const int g    = lane >> 2;
    const int q    = lane & 3;

    const int bh = blockIdx.y;
    const float* Qg = g_Q + (size_t)bh * SEQ * HDIM;
    const float* Kg = g_K + (size_t)bh * SEQ * HDIM;
    const float* Vg = g_V + (size_t)bh * SEQ * HDIM;

    const int q0 = blockIdx.x * 128 + w * 16;

    unsigned qa[8][4];
#pragma unroll
    for (int kt = 0; kt < 8; kt++) {
        int c0 = kt * 8 + q;
        qa[kt][0] = __float_as_uint(Qg[(size_t)(q0 + g)     * HDIM + c0]);
        qa[kt][1] = __float_as_uint(Qg[(size_t)(q0 + g + 8) * HDIM + c0]);
        qa[kt][2] = __float_as_uint(Qg[(size_t)(q0 + g)     * HDIM + c0 + 4]);
        qa[kt][3] = __float_as_uint(Qg[(size_t)(q0 + g + 8) * HDIM + c0 + 4]);
    }

    float o[8][4];
#pragma unroll
    for (int dt = 0; dt < 8; dt++)
        o[dt][0] = o[dt][1] = o[dt][2] = o[dt][3] = 0.0f;
    float mrow0 = -INFINITY, mrow1 = -INFINITY;
    float lrow0 = 0.0f, lrow1 = 0.0f;

    stage_kv(sm, 0, Kg, Vg, 0,  tid);
    stage_kv(sm, 1, Kg, Vg, KT, tid);

    constexpr int NT = SEQ / KT;
    for (int t = 0; t < NT; t++) {
        const int buf = t & 1;
        if (t + 1 < NT) { CP_WAIT1(); } else { CP_WAIT0(); }
        __syncthreads();

        float s[4][4];
#pragma unroll
        for (int nt = 0; nt < 4; nt++)
            s[nt][0] = s[nt][1] = s[nt][2] = s[nt][3] = 0.0f;
#pragma unroll
        for (int kt = 0; kt < 8; kt++) {
#pragma unroll
            for (int nt = 0; nt < 4; nt++) {
                unsigned b0 = __float_as_uint(KS(buf, nt * 8 + g, kt * 8 + q));
                unsigned b1 = __float_as_uint(KS(buf, nt * 8 + g, kt * 8 + q + 4));
                mma_tf32(s[nt], qa[kt], b0, b1);
            }
        }

        float rm0 = -INFINITY, rm1 = -INFINITY;
#pragma unroll
        for (int nt = 0; nt < 4; nt++) {
            rm0 = fmaxf(rm0, fmaxf(s[nt][0], s[nt][1]));
            rm1 = fmaxf(rm1, fmaxf(s[nt][2], s[nt][3]));
        }
        rm0 = fmaxf(rm0, __shfl_xor_sync(0xffffffffu, rm0, 1));
        rm0 = fmaxf(rm0, __shfl_xor_sync(0xffffffffu, rm0, 2));
        rm1 = fmaxf(rm1, __shfl_xor_sync(0xffffffffu, rm1, 1));
        rm1 = fmaxf(rm1, __shfl_xor_sync(0xffffffffu, rm1, 2));

        float mn0 = fmaxf(mrow0, rm0);
        float mn1 = fmaxf(mrow1, rm1);

        bool chg = (mn0 > mrow0) || (mn1 > mrow1);
        if (__ballot_sync(0xffffffffu, chg)) {
            float al0 = fexp2(mrow0 - mn0);
            float al1 = fexp2(mrow1 - mn1);
            lrow0 *= al0;
            lrow1 *= al1;
#pragma unroll
            for (int dt = 0; dt < 8; dt++) {
                o[dt][0] *= al0; o[dt][1] *= al0;
                o[dt][2] *= al1; o[dt][3] *= al1;
            }
            mrow0 = mn0;
            mrow1 = mn1;
        }

        float ps0 = 0.0f, ps1 = 0.0f;
#pragma unroll
        for (int nt = 0; nt < 4; nt++) {
            s[nt][0] = fexp2(s[nt][0] - mrow0);
            s[nt][1] = fexp2(s[nt][1] - mrow0);
            s[nt][2] = fexp2(s[nt][2] - mrow1);
            s[nt][3] = fexp2(s[nt][3] - mrow1);
            ps0 += s[nt][0] + s[nt][1];
            ps1 += s[nt][2] + s[nt][3];
        }
        ps0 += __shfl_xor_sync(0xffffffffu, ps0, 1);
        ps0 += __shfl_xor_sync(0xffffffffu, ps0, 2);
        ps1 += __shfl_xor_sync(0xffffffffu, ps1, 1);
        ps1 += __shfl_xor_sync(0xffffffffu, ps1, 2);

        lrow0 += ps0;
        lrow1 += ps1;

        const int srcA = (lane & ~3) | (q >> 1);
        const int srcB = srcA + 2;
        const bool odd = (q & 1);
#pragma unroll
        for (int kt = 0; kt < 4; kt++) {
            float u0 = __shfl_sync(0xffffffffu, s[kt][0], srcA);
            float u1 = __shfl_sync(0xffffffffu, s[kt][1], srcA);
            float u2 = __shfl_sync(0xffffffffu, s[kt][2], srcA);
            float u3 = __shfl_sync(0xffffffffu, s[kt][3], srcA);
            float v0 = __shfl_sync(0xffffffffu, s[kt][0], srcB);
            float v1 = __shfl_sync(0xffffffffu, s[kt][1], srcB);
            float v2 = __shfl_sync(0xffffffffu, s[kt][2], srcB);
            float v3 = __shfl_sync(0xffffffffu, s[kt][3], srcB);
            unsigned pa[4];
            pa[0] = f2tf(odd ? u1 : u0);
            pa[1] = f2tf(odd ? u3 : u2);
            pa[2] = f2tf(odd ? v1 : v0);
            pa[3] = f2tf(odd ? v3 : v2);
#pragma unroll
            for (int dt = 0; dt < 8; dt++) {
                unsigned b0 = __float_as_uint(VS(buf, kt * 8 + q,     dt * 8 + g));
                unsigned b1 = __float_as_uint(VS(buf, kt * 8 + q + 4, dt * 8 + g));
                mma_tf32(o[dt], pa, b0, b1);
            }
        }

        __syncthreads();
        if (t + 2 < NT) {
            stage_kv(sm, buf, Kg, Vg, (t + 2) * KT, tid);
        }
    }

    // epilogue: O/l -> g_AO [B,N,H,Dh], pre-rounded to tf32 for the proj GEMM
    const float il0 = 1.0f / lrow0;
    const float il1 = 1.0f / lrow1;
    const int b = bh >> 4, h = bh & 15;
    const int n0g = blockIdx.x * 128 + w * 16 + g;
    const size_t base0 = (((size_t)b * SEQ + n0g)     * NHEADS + h) * HDIM;
    const size_t base1 = (((size_t)b * SEQ + n0g + 8) * NHEADS + h) * HDIM;
#pragma unroll
    for (int dt = 0; dt < 8; dt++) {
        g_AO[base0 + dt * 8 + 2 * q]     = __uint_as_float(f2tf(o[dt][0] * il0));
        g_AO[base0 + dt * 8 + 2 * q + 1] = __uint_as_float(f2tf(o[dt][1] * il0));
        g_AO[base1 + dt * 8 + 2 * q]     = __uint_as_float(f2tf(o[dt][2] * il1));
        g_AO[base1 + dt * 8 + 2 * q + 1] = __uint_as_float(f2tf(o[dt][3] * il1));
    }
}

extern "C" void kernel_launch(void* const* d_in, const int* in_sizes, int n_in,
                              void* d_out, int out_size)
{
    (void)in_sizes; (void)n_in; (void)out_size;
    const float* x     = (const float*)d_in[0];   // [4,2048,1024]
    const float* wqkv  = (const float*)d_in[1];   // [3072,1024]
    const float* wproj = (const float*)d_in[2];   // [1024,1024]
    const float* bproj = (const float*)d_in[3];   // [1024]
    float* out = (float*)d_out;                   // [4,2048,1024]

    cudaFuncSetAttribute(attn_kernel,
                         cudaFuncAttributeMaxDynamicSharedMemorySize,
                         ATT_SMEM_BYTES);
    cudaFuncSetAttribute(gemm_tf32_kernel<0>,
                         cudaFuncAttributeMaxDynamicSharedMemorySize,
                         GEMM_SMEM_BYTES);
    cudaFuncSetAttribute(gemm_tf32_kernel<1>,
                         cudaFuncAttributeMaxDynamicSharedMemorySize,
                         GEMM_SMEM_BYTES);

    float *xt, *wqt, *wpt;
    cudaGetSymbolAddress((void**)&xt,  g_Xt);
    cudaGetSymbolAddress((void**)&wqt, g_Wqt);
    cudaGetSymbolAddress((void**)&wpt, g_Wpt);

    // 1) pre-round GEMM inputs to tf32 bits
    round_tf32_kernel<<<(MTOT * DIMC / 4 + 255) / 256, 256>>>(
        (const float4*)x, (float4*)xt, MTOT * DIMC / 4);
    round_tf32_kernel<<<(3 * DIMC * DIMC / 4 + 255) / 256, 256>>>(
        (const float4*)wqkv, (float4*)wqt, 3 * DIMC * DIMC / 4);
    round_tf32_kernel<<<(DIMC * DIMC / 4 + 255) / 256, 256>>>(
        (const float4*)wproj, (float4*)wpt, DIMC * DIMC / 4);

    // 2) QKV GEMM -> g_Q/g_K/g_V
    gemm_tf32_kernel<0><<<dim3(3 * DIMC / 128, MTOT / 128), 256, GEMM_SMEM_BYTES>>>(
        xt, wqt, nullptr, nullptr, MTOT, 3 * DIMC, DIMC);

    // 3) attention -> g_AO
    attn_kernel<<<dim3(SEQ / 128, BATCH * NHEADS), 256, ATT_SMEM_BYTES>>>();

    // 4) projection GEMM (+fused bias) -> out
    gemm_tf32_kernel<1><<<dim3(DIMC / 128, MTOT / 128), 256, GEMM_SMEM_BYTES>>>(
        nullptr, wpt, bproj, out, MTOT, DIMC, DIMC);
}